// round 9
// baseline (speedup 1.0000x reference)
#include <cuda_runtime.h>
#include <cuda_bf16.h>
#include <cstdint>
#include <cstddef>

// ---------------- problem dims ----------------
constexpr int TT    = 4;
constexpr int BROWS = 8192;           // B*N
constexpr int DD    = 512;
constexpr int HH    = 2048;
constexpr int KQ1   = 1024;           // layer1 int8 K: [q(lo_x) | q(x)]
constexpr int KH1   = 512;            // layer1 bf16 K (hi*hi)
constexpr int KA2   = 2048;           // layer2 A cols (s1 int8, wraps)
constexpr int KB2   = 6144;           // layer2 K: 3 digit planes x 2048 int8

// layer1 quantization scales (fixed, generous bounds: |x|<8, |w1|<0.32)
constexpr float IXH = 127.0f / 8.0f;             // q(x)    = rn(x * IXH)
constexpr float IXL = 512.0f * 127.0f / 8.0f;    // q(lo_x) = rn(lo * IXL)
constexpr float IWH = 127.0f / 0.32f;            // q(hi_w)
constexpr float IWL = 512.0f * 127.0f / 0.32f;   // q(lo_w)
constexpr float CFOLD = (float)((8.0 * 0.32) / (512.0 * 127.0 * 127.0)); // 3.1e-7
constexpr float EPS = 2e-3f;                     // margin-repair threshold

// W2 fixed-point scale (layer2, exact 3-digit scheme)
constexpr float W2SCALE = 1.0f / 4194304.0f;     // 2^-22

// ---- layer1 tile: CTA 32 x 128 x 4t, 8 warps of 16x32 (R5-proven) ----
constexpr int MS1 = 32, TN1 = 128, STG = 3;
constexpr uint32_t A1_STAGE = 16384;   // 4t x 32 x 128B
constexpr uint32_t B1_STAGE = 16384;   // 128 x 128B
constexpr uint32_t SM1_B = STG * A1_STAGE;
constexpr uint32_t SMEM1 = STG * (A1_STAGE + B1_STAGE);   // 98304

// ---- layer2 tile (R8-proven): CTA 32x128x4t int8, BK=128 ----
constexpr int MS2 = 32, TN2 = 128, BK2 = 128;
constexpr uint32_t A2_STAGE = 16384;
constexpr uint32_t B2_STAGE = 16384;
constexpr uint32_t SM2_B = STG * A2_STAGE;
constexpr uint32_t SMEM2 = STG * (A2_STAGE + B2_STAGE);   // 98304

// ---------------- scratch ----------------
__device__ __nv_bfloat16 g_xh[(size_t)TT * BROWS * KH1];   // bf16(x)
__device__ int8_t        g_xq[(size_t)TT * BROWS * KQ1];   // [q(lo_x)|q(x)]
__device__ __nv_bfloat16 g_w1h[(size_t)HH * KH1];          // bf16(w1)
__device__ int8_t        g_w1q[(size_t)HH * KQ1];          // [q(hi_w)|q(lo_w)]
__device__ int8_t        g_w2[(size_t)DD * KB2];           // 3 digit planes
__device__ int8_t        g_s1[(size_t)TT * BROWS * HH];    // spikes layer1 (0/1)

// ---------------- PTX helpers ----------------
__device__ __forceinline__ uint32_t smem_u32(const void* p) {
    uint32_t a;
    asm("{ .reg .u64 t; cvta.to.shared.u64 t, %1; cvt.u32.u64 %0, t; }" : "=r"(a) : "l"(p));
    return a;
}
#define CP_ASYNC16(dst, src) \
    asm volatile("cp.async.cg.shared.global [%0], [%1], 16;" :: "r"(dst), "l"(src) : "memory")
#define CP_COMMIT() asm volatile("cp.async.commit_group;" ::: "memory")

#define LDSM_X4(r0, r1, r2, r3, addr)                                        \
    asm volatile("ldmatrix.sync.aligned.m8n8.x4.shared.b16 {%0,%1,%2,%3}, [%4];" \
        : "=r"(r0), "=r"(r1), "=r"(r2), "=r"(r3) : "r"(addr))

#define MMA16816(d, a, b)                                                    \
    asm volatile("mma.sync.aligned.m16n8k16.row.col.f32.bf16.bf16.f32 "      \
        "{%0,%1,%2,%3}, {%4,%5,%6,%7}, {%8,%9}, {%0,%1,%2,%3};"              \
        : "+f"((d)[0]), "+f"((d)[1]), "+f"((d)[2]), "+f"((d)[3])             \
        : "r"((a)[0]), "r"((a)[1]), "r"((a)[2]), "r"((a)[3]),                \
          "r"((b)[0]), "r"((b)[1]))

#define IMMA16832(d, a, b)                                                   \
    asm volatile("mma.sync.aligned.m16n8k32.row.col.s32.s8.s8.s32 "          \
        "{%0,%1,%2,%3}, {%4,%5,%6,%7}, {%8,%9}, {%0,%1,%2,%3};"              \
        : "+r"((d)[0]), "+r"((d)[1]), "+r"((d)[2]), "+r"((d)[3])             \
        : "r"((a)[0]), "r"((a)[1]), "r"((a)[2]), "r"((a)[3]),                \
          "r"((b)[0]), "r"((b)[1]))

// XOR swizzle: 128B rows, 8 x 16B segments, kseg ^= row&7
__device__ __forceinline__ uint32_t sw_off(uint32_t row, uint32_t kseg) {
    return row * 128 + ((kseg ^ (row & 7)) << 4);
}
__device__ __forceinline__ int8_t q8(float v, float inv) {
    int q = __float2int_rn(v * inv);
    q = max(-127, min(127, q));
    return (int8_t)q;
}

// ---------------- prep kernels ----------------
__global__ void prep_x(const float4* __restrict__ x,
                       __nv_bfloat16* __restrict__ xh,
                       int8_t* __restrict__ xq)
{
    size_t i = (size_t)blockIdx.x * blockDim.x + threadIdx.x;   // 32768*128 float4
    float4 v = x[i];
    int r = (int)(i >> 7);
    int d = ((int)i & 127) * 4;
    __nv_bfloat16 h0 = __float2bfloat16(v.x), h1 = __float2bfloat16(v.y);
    __nv_bfloat16 h2 = __float2bfloat16(v.z), h3 = __float2bfloat16(v.w);
    __nv_bfloat162* hp = (__nv_bfloat162*)(xh + (size_t)r * KH1 + d);
    hp[0] = __nv_bfloat162(h0, h1);
    hp[1] = __nv_bfloat162(h2, h3);
    float l0 = v.x - __bfloat162float(h0), l1 = v.y - __bfloat162float(h1);
    float l2 = v.z - __bfloat162float(h2), l3 = v.w - __bfloat162float(h3);
    char4 ql = make_char4(q8(l0, IXL), q8(l1, IXL), q8(l2, IXL), q8(l3, IXL));
    char4 qx = make_char4(q8(v.x, IXH), q8(v.y, IXH), q8(v.z, IXH), q8(v.w, IXH));
    *(char4*)(xq + (size_t)r * KQ1 + d)       = ql;
    *(char4*)(xq + (size_t)r * KQ1 + 512 + d) = qx;
}
__global__ void prep_w1(const float* __restrict__ w,
                        __nv_bfloat16* __restrict__ wh,
                        int8_t* __restrict__ wq)
{
    size_t i = (size_t)blockIdx.x * blockDim.x + threadIdx.x;   // 2048*512
    int r = (int)(i >> 9);
    int d = (int)(i & 511);
    float v = w[i];
    __nv_bfloat16 hb = __float2bfloat16(v);
    float hi = __bfloat162float(hb);
    wh[(size_t)r * KH1 + d] = hb;
    wq[(size_t)r * KQ1 + d]       = q8(hi, IWH);
    wq[(size_t)r * KQ1 + 512 + d] = q8(v - hi, IWL);
}
__global__ void pack_w2(const float* __restrict__ w, int8_t* __restrict__ o)
{
    size_t i = (size_t)blockIdx.x * blockDim.x + threadIdx.x;   // 512*2048
    int r = (int)(i >> 11);
    int c = (int)(i & 2047);
    int v = (int)lrintf(w[i] * 4194304.0f);
    int a0 = ((v & 127) ^ 64) - 64;
    int v1 = (v - a0) >> 7;
    int a1 = ((v1 & 127) ^ 64) - 64;
    int a2 = (v1 - a1) >> 7;
    size_t base = (size_t)r * KB2;
    o[base + c]        = (int8_t)a2;
    o[base + 2048 + c] = (int8_t)a1;
    o[base + 4096 + c] = (int8_t)a0;
}

// ---------------- layer1: int8 cross + bf16 hi*hi + PLIF + margin repair ----
__global__ __launch_bounds__(256, 1)
void gemm_plif_l1(const int8_t* __restrict__ Aq, const int8_t* __restrict__ Bq,
                  const __nv_bfloat16* __restrict__ Ah,
                  const __nv_bfloat16* __restrict__ Bh,
                  const float* __restrict__ xraw, const float* __restrict__ w1raw,
                  const float* __restrict__ alphap,
                  int8_t* __restrict__ outp)
{
    extern __shared__ __align__(128) unsigned char smem_raw[];
    const uint32_t sbase = smem_u32(smem_raw);

    const int tid  = threadIdx.x;
    const int lane = tid & 31;
    const int wid  = tid >> 5;
    const int wm   = wid & 1;           // 2 warps over sites (16 each)
    const int wn   = wid >> 1;          // 4 warps over cols (32 each)
    const int sm_w = wm * 16;
    const int nn_w = wn * 32;

    const int bm0 = blockIdx.x * MS1;
    const int bn0 = blockIdx.y * TN1;

    const int a_row_l = lane & 15;
    const int a_ks_l  = lane >> 4;
    const int b_row_l = (lane & 7) + ((lane & 16) >> 1);
    const int b_ks_l  = (lane >> 3) & 1;

    // ---- phase 1: int8 cross terms, K=1024, 8 chunks of BK=128 ----
    auto loadq = [&](int cc, int buf) {
        const int col = cc * 128;
        #pragma unroll
        for (int i = tid; i < 1024; i += 256) {      // A: 4t*32 rows*8 segs
            int kseg = i & 7, site = (i >> 3) & 31, t = i >> 8;
            const int8_t* g =
                Aq + ((size_t)t * BROWS + bm0 + site) * KQ1 + col + kseg * 16;
            CP_ASYNC16(sbase + buf * A1_STAGE + t * 4096 + sw_off(site, kseg), g);
        }
        #pragma unroll
        for (int i = tid; i < 1024; i += 256) {      // B: 128 rows*8 segs
            int kseg = i & 7, n = i >> 3;
            const int8_t* g =
                Bq + (size_t)(bn0 + n) * KQ1 + col + kseg * 16;
            CP_ASYNC16(sbase + SM1_B + buf * B1_STAGE + sw_off(n, kseg), g);
        }
        CP_COMMIT();
    };

    int acci[TT][4][4];
    #pragma unroll
    for (int t = 0; t < TT; t++)
        #pragma unroll
        for (int n = 0; n < 4; n++)
            #pragma unroll
            for (int e = 0; e < 4; e++) acci[t][n][e] = 0;

    loadq(0, 0);
    loadq(1, 1);
    for (int cc = 0; cc < 8; cc++) {
        const int buf = cc % STG;
        if (cc < 7) asm volatile("cp.async.wait_group 1;" ::: "memory");
        else        asm volatile("cp.async.wait_group 0;" ::: "memory");
        __syncthreads();
        if (cc + 2 < 8) loadq(cc + 2, (cc + 2) % STG);

        #pragma unroll
        for (int ks = 0; ks < 4; ks++) {
            uint32_t b[4][2];
            #pragma unroll
            for (int p = 0; p < 2; p++) {
                uint32_t addr = sbase + SM1_B + buf * B1_STAGE +
                    sw_off(nn_w + p * 16 + b_row_l, 2 * ks + b_ks_l);
                LDSM_X4(b[2*p][0], b[2*p][1], b[2*p+1][0], b[2*p+1][1], addr);
            }
            uint32_t a[TT][4];
            #pragma unroll
            for (int t = 0; t < TT; t++) {
                uint32_t addr = sbase + buf * A1_STAGE + t * 4096 +
                    sw_off(sm_w + a_row_l, 2 * ks + a_ks_l);
                LDSM_X4(a[t][0], a[t][1], a[t][2], a[t][3], addr);
            }
            #pragma unroll
            for (int t = 0; t < TT; t++)
                #pragma unroll
                for (int n = 0; n < 4; n++)
                    IMMA16832(acci[t][n], a[t], b[n]);
        }
    }
    __syncthreads();

    // fold int8 accumulator -> fp32 (acci dies here)
    float accf[TT][4][4];
    #pragma unroll
    for (int t = 0; t < TT; t++)
        #pragma unroll
        for (int n = 0; n < 4; n++)
            #pragma unroll
            for (int e = 0; e < 4; e++)
                accf[t][n][e] = CFOLD * (float)acci[t][n][e];

    // ---- phase 2: bf16 hi*hi, K=512, 8 chunks of BK=64 ----
    auto loadh = [&](int cc, int buf) {
        const int col = cc * 64;
        #pragma unroll
        for (int i = tid; i < 1024; i += 256) {
            int kseg = i & 7, site = (i >> 3) & 31, t = i >> 8;
            const __nv_bfloat16* g =
                Ah + ((size_t)t * BROWS + bm0 + site) * KH1 + col + kseg * 8;
            CP_ASYNC16(sbase + buf * A1_STAGE + t * 4096 + sw_off(site, kseg), g);
        }
        #pragma unroll
        for (int i = tid; i < 1024; i += 256) {
            int kseg = i & 7, n = i >> 3;
            const __nv_bfloat16* g =
                Bh + (size_t)(bn0 + n) * KH1 + col + kseg * 8;
            CP_ASYNC16(sbase + SM1_B + buf * B1_STAGE + sw_off(n, kseg), g);
        }
        CP_COMMIT();
    };

    loadh(0, 0);
    loadh(1, 1);
    for (int cc = 0; cc < 8; cc++) {
        const int buf = cc % STG;
        if (cc < 7) asm volatile("cp.async.wait_group 1;" ::: "memory");
        else        asm volatile("cp.async.wait_group 0;" ::: "memory");
        __syncthreads();
        if (cc + 2 < 8) loadh(cc + 2, (cc + 2) % STG);

        #pragma unroll
        for (int ks = 0; ks < 4; ks++) {
            uint32_t b[4][2];
            #pragma unroll
            for (int p = 0; p < 2; p++) {
                uint32_t addr = sbase + SM1_B + buf * B1_STAGE +
                    sw_off(nn_w + p * 16 + b_row_l, 2 * ks + b_ks_l);
                LDSM_X4(b[2*p][0], b[2*p][1], b[2*p+1][0], b[2*p+1][1], addr);
            }
            uint32_t a[TT][4];
            #pragma unroll
            for (int t = 0; t < TT; t++) {
                uint32_t addr = sbase + buf * A1_STAGE + t * 4096 +
                    sw_off(sm_w + a_row_l, 2 * ks + a_ks_l);
                LDSM_X4(a[t][0], a[t][1], a[t][2], a[t][3], addr);
            }
            #pragma unroll
            for (int t = 0; t < TT; t++)
                #pragma unroll
                for (int n = 0; n < 4; n++)
                    MMA16816(accf[t][n], a[t], b[n]);
        }
    }

    // ---- epilogue: PLIF scan + threshold-margin repair ----
    const float alpha = alphap[0];
    const int row_in_m = lane >> 2;
    const int col_pair = (lane & 3) * 2;

    #pragma unroll
    for (int n = 0; n < 4; n++)
        #pragma unroll
        for (int rh = 0; rh < 2; rh++) {
            const int site = bm0 + sm_w + row_in_m + rh * 8;
            const int col  = bn0 + nn_w + n * 8 + col_pair;
            float hv[2][TT];
            #pragma unroll
            for (int t = 0; t < TT; t++) {
                hv[0][t] = accf[t][n][rh * 2];
                hv[1][t] = accf[t][n][rh * 2 + 1];
            }
            #pragma unroll
            for (int j = 0; j < 2; j++) {
                // scan with margin check
                float v = 0.f, minm = 1e9f;
                #pragma unroll
                for (int t = 0; t < TT; t++) {
                    v += alpha * (hv[j][t] - v);
                    minm = fminf(minm, fabsf(v - 1.0f));
                    bool s = (v >= 1.0f);
                    v = s ? 0.f : v;
                }
                if (minm < EPS) {   // rare: exact recompute from fp32 inputs
                    const int neuron = col + j;
                    const float4* wp = (const float4*)(w1raw + (size_t)neuron * 512);
                    for (int t = 0; t < TT; t++) {
                        const float4* xp = (const float4*)(xraw +
                            ((size_t)t * BROWS + site) * 512);
                        float a0 = 0.f, a1 = 0.f, a2 = 0.f, a3 = 0.f;
                        for (int k = 0; k < 128; k++) {
                            float4 xv = xp[k], wv = wp[k];
                            a0 += xv.x * wv.x; a1 += xv.y * wv.y;
                            a2 += xv.z * wv.z; a3 += xv.w * wv.w;
                        }
                        hv[j][t] = (a0 + a1) + (a2 + a3);
                    }
                }
            }
            // final scan + store
            float v0 = 0.f, v1 = 0.f;
            #pragma unroll
            for (int t = 0; t < TT; t++) {
                v0 += alpha * (hv[0][t] - v0);
                v1 += alpha * (hv[1][t] - v1);
                bool s0 = (v0 >= 1.0f), s1 = (v1 >= 1.0f);
                v0 = s0 ? 0.f : v0;
                v1 = s1 ? 0.f : v1;
                char2 pk;
                pk.x = s0 ? 1 : 0;
                pk.y = s1 ? 1 : 0;
                *(char2*)(outp + ((size_t)t * BROWS + site) * HH + col) = pk;
            }
        }
}

// ---------------- layer2: int8 IMMA 3-digit exact + PLIF (R8-proven) ----------------
__global__ __launch_bounds__(256, 1)
void gemm_plif_l2(const int8_t* __restrict__ A,
                  const int8_t* __restrict__ Bw,
                  const float* __restrict__ alphap,
                  float* __restrict__ outp)
{
    extern __shared__ __align__(128) unsigned char smem_raw[];
    const uint32_t sbase = smem_u32(smem_raw);

    const int tid  = threadIdx.x;
    const int lane = tid & 31;
    const int wid  = tid >> 5;
    const int wm   = wid & 1;
    const int wn   = wid >> 1;
    const int sm_w = wm * 16;
    const int nn_w = wn * 32;

    const int bm0 = blockIdx.x * MS2;
    const int bn0 = blockIdx.y * TN2;
    const int NC  = KB2 / BK2;          // 48

    auto load_chunk = [&](int cc, int buf) {
        const int acol = (cc * BK2) % KA2;
        const int bcol = cc * BK2;
        #pragma unroll
        for (int i = tid; i < 1024; i += 256) {
            int kseg = i & 7, site = (i >> 3) & 31, t = i >> 8;
            const int8_t* g =
                A + ((size_t)t * BROWS + bm0 + site) * KA2 + acol + kseg * 16;
            CP_ASYNC16(sbase + buf * A2_STAGE + t * 4096 + sw_off(site, kseg), g);
        }
        #pragma unroll
        for (int i = tid; i < 1024; i += 256) {
            int kseg = i & 7, n = i >> 3;
            const int8_t* g =
                Bw + (size_t)(bn0 + n) * KB2 + bcol + kseg * 16;
            CP_ASYNC16(sbase + SM2_B + buf * B2_STAGE + sw_off(n, kseg), g);
        }
        CP_COMMIT();
    };

    int acc[TT][4][4];
    #pragma unroll
    for (int t = 0; t < TT; t++)
        #pragma unroll
        for (int n = 0; n < 4; n++)
            #pragma unroll
            for (int e = 0; e < 4; e++) acc[t][n][e] = 0;

    load_chunk(0, 0);
    load_chunk(1, 1);

    const int a_row_l = lane & 15;
    const int a_ks_l  = lane >> 4;
    const int b_row_l = (lane & 7) + ((lane & 16) >> 1);
    const int b_ks_l  = (lane >> 3) & 1;

    for (int cc = 0; cc < NC; cc++) {
        const int buf = cc % STG;
        if (cc < NC - 1) asm volatile("cp.async.wait_group 1;" ::: "memory");
        else             asm volatile("cp.async.wait_group 0;" ::: "memory");
        __syncthreads();
        if (cc + 2 < NC) load_chunk(cc + 2, (cc + 2) % STG);

        #pragma unroll
        for (int ks = 0; ks < 4; ks++) {
            uint32_t b[4][2];
            #pragma unroll
            for (int p = 0; p < 2; p++) {
                uint32_t addr = sbase + SM2_B + buf * B2_STAGE +
                    sw_off(nn_w + p * 16 + b_row_l, 2 * ks + b_ks_l);
                LDSM_X4(b[2*p][0], b[2*p][1], b[2*p+1][0], b[2*p+1][1], addr);
            }
            uint32_t a[TT][4];
            #pragma unroll
            for (int t = 0; t < TT; t++) {
                uint32_t addr = sbase + buf * A2_STAGE + t * 4096 +
                    sw_off(sm_w + a_row_l, 2 * ks + a_ks_l);
                LDSM_X4(a[t][0], a[t][1], a[t][2], a[t][3], addr);
            }
            #pragma unroll
            for (int t = 0; t < TT; t++)
                #pragma unroll
                for (int n = 0; n < 4; n++)
                    IMMA16832(acc[t][n], a[t], b[n]);
        }

        if (cc == 15 || cc == 31) {
            #pragma unroll
            for (int t = 0; t < TT; t++)
                #pragma unroll
                for (int n = 0; n < 4; n++)
                    #pragma unroll
                    for (int e = 0; e < 4; e++) acc[t][n][e] <<= 7;
        }
    }

    const float alpha = alphap[0];
    float sp_out[TT][4][4];
    #pragma unroll
    for (int n = 0; n < 4; n++)
        #pragma unroll
        for (int e = 0; e < 4; e++) {
            float v = 0.f;
            #pragma unroll
            for (int t = 0; t < TT; t++) {
                float y = (float)acc[t][n][e] * W2SCALE;
                v += alpha * (y - v);
                bool sp = (v >= 1.0f);
                sp_out[t][n][e] = sp ? 1.0f : 0.0f;
                v = sp ? 0.f : v;
            }
        }

    const int row_in_m = lane >> 2;
    const int col_pair = (lane & 3) * 2;
    #pragma unroll
    for (int t = 0; t < TT; t++)
        #pragma unroll
        for (int rh = 0; rh < 2; rh++) {
            int site = bm0 + sm_w + row_in_m + rh * 8;
            #pragma unroll
            for (int n = 0; n < 4; n++) {
                int col = bn0 + nn_w + n * 8 + col_pair;
                *(float2*)(outp + ((size_t)t * BROWS + site) * DD + col) =
                    make_float2(sp_out[t][n][rh * 2], sp_out[t][n][rh * 2 + 1]);
            }
        }
}

// ---------------- launch ----------------
extern "C" void kernel_launch(void* const* d_in, const int* in_sizes, int n_in,
                              void* d_out, int out_size)
{
    const float* x  = (const float*)d_in[0];
    const float* W1 = (const float*)d_in[1];
    const float* W2 = (const float*)d_in[2];
    const float* a1 = (const float*)d_in[3];
    const float* a2 = (const float*)d_in[4];
    float* out = (float*)d_out;

    __nv_bfloat16 *xh, *w1h;
    int8_t *xq, *w1q, *w2p, *s1;
    cudaGetSymbolAddress((void**)&xh,  g_xh);
    cudaGetSymbolAddress((void**)&xq,  g_xq);
    cudaGetSymbolAddress((void**)&w1h, g_w1h);
    cudaGetSymbolAddress((void**)&w1q, g_w1q);
    cudaGetSymbolAddress((void**)&w2p, g_w2);
    cudaGetSymbolAddress((void**)&s1,  g_s1);

    cudaFuncSetAttribute(gemm_plif_l1, cudaFuncAttributeMaxDynamicSharedMemorySize, SMEM1);
    cudaFuncSetAttribute(gemm_plif_l2, cudaFuncAttributeMaxDynamicSharedMemorySize, SMEM2);

    prep_x<<<(TT * BROWS * DD / 4) / 256, 256>>>((const float4*)x, xh, xq);
    prep_w1<<<(HH * DD) / 256, 256>>>(W1, w1h, w1q);
    pack_w2<<<(DD * HH) / 256, 256>>>(W2, w2p);

    // layer 1: int8 cross (K=1024) + bf16 hi*hi (K=512) + margin repair -> s1
    dim3 g1(BROWS / MS1, HH / TN1);   // 256 x 16
    gemm_plif_l1<<<g1, 256, SMEM1>>>(xq, w1q, xh, w1h, x, W1, a1, s1);

    // layer 2: int8 IMMA 3-digit exact, K=6144 -> out fp32 spikes
    dim3 g2(BROWS / MS2, DD / TN2);   // 256 x 4
    gemm_plif_l2<<<g2, 256, SMEM2>>>(s1, w2p, a2, out);
}

// round 10
// speedup vs baseline: 1.8983x; 1.8983x over previous
#include <cuda_runtime.h>
#include <cuda_bf16.h>
#include <cstdint>
#include <cstddef>

// ---------------- problem dims ----------------
constexpr int TT    = 4;
constexpr int BROWS = 8192;           // B*N
constexpr int DD    = 512;
constexpr int HH    = 2048;
constexpr int KQ1   = 1024;           // layer1 int8 K: [q(lo_x) | q(x)]
constexpr int KH1   = 512;            // layer1 bf16 K (hi*hi)
constexpr int KA2   = 2048;           // layer2 A cols (s1 int8, wraps)
constexpr int KB2   = 6144;           // layer2 K: 3 digit planes x 2048 int8

// layer1 quantization scales (fixed bounds: |x|<8, |w1|<0.32)
constexpr float IXH = 127.0f / 8.0f;
constexpr float IXL = 512.0f * 127.0f / 8.0f;
constexpr float IWH = 127.0f / 0.32f;
constexpr float IWL = 512.0f * 127.0f / 0.32f;
constexpr float CFOLD = (float)((8.0 * 0.32) / (512.0 * 127.0 * 127.0));
constexpr float EPS = 1e-3f;          // margin flag threshold (~10 sigma)

constexpr float W2SCALE = 1.0f / 4194304.0f;     // 2^-22 (layer2 exact)

// ---- layer1 tile: CTA 32 x 128 x 4t, 8 warps of 16x32 ----
constexpr int MS1 = 32, TN1 = 128, STG = 3;
constexpr uint32_t A1_STAGE = 16384;
constexpr uint32_t B1_STAGE = 16384;
constexpr uint32_t SM1_B = STG * A1_STAGE;
constexpr uint32_t SMEM1 = STG * (A1_STAGE + B1_STAGE);   // 98304

// ---- layer2 tile (R8-proven) ----
constexpr int MS2 = 32, TN2 = 128, BK2 = 128;
constexpr uint32_t A2_STAGE = 16384;
constexpr uint32_t B2_STAGE = 16384;
constexpr uint32_t SM2_B = STG * A2_STAGE;
constexpr uint32_t SMEM2 = STG * (A2_STAGE + B2_STAGE);   // 98304

// ---------------- scratch ----------------
__device__ __nv_bfloat16 g_xh[(size_t)TT * BROWS * KH1];
__device__ int8_t        g_xq[(size_t)TT * BROWS * KQ1];
__device__ __nv_bfloat16 g_w1h[(size_t)HH * KH1];
__device__ int8_t        g_w1q[(size_t)HH * KQ1];
__device__ int8_t        g_w2[(size_t)DD * KB2];
__device__ int8_t        g_s1[(size_t)TT * BROWS * HH];
constexpr int LCAP = 1 << 22;
__device__ int g_cnt;
__device__ int g_list[LCAP];

// ---------------- PTX helpers ----------------
__device__ __forceinline__ uint32_t smem_u32(const void* p) {
    uint32_t a;
    asm("{ .reg .u64 t; cvta.to.shared.u64 t, %1; cvt.u32.u64 %0, t; }" : "=r"(a) : "l"(p));
    return a;
}
#define CP_ASYNC16(dst, src) \
    asm volatile("cp.async.cg.shared.global [%0], [%1], 16;" :: "r"(dst), "l"(src) : "memory")
#define CP_COMMIT() asm volatile("cp.async.commit_group;" ::: "memory")

#define LDSM_X4(r0, r1, r2, r3, addr)                                        \
    asm volatile("ldmatrix.sync.aligned.m8n8.x4.shared.b16 {%0,%1,%2,%3}, [%4];" \
        : "=r"(r0), "=r"(r1), "=r"(r2), "=r"(r3) : "r"(addr))

#define MMA16816(d, a, b)                                                    \
    asm volatile("mma.sync.aligned.m16n8k16.row.col.f32.bf16.bf16.f32 "      \
        "{%0,%1,%2,%3}, {%4,%5,%6,%7}, {%8,%9}, {%0,%1,%2,%3};"              \
        : "+f"((d)[0]), "+f"((d)[1]), "+f"((d)[2]), "+f"((d)[3])             \
        : "r"((a)[0]), "r"((a)[1]), "r"((a)[2]), "r"((a)[3]),                \
          "r"((b)[0]), "r"((b)[1]))

#define IMMA16832(d, a, b)                                                   \
    asm volatile("mma.sync.aligned.m16n8k32.row.col.s32.s8.s8.s32 "          \
        "{%0,%1,%2,%3}, {%4,%5,%6,%7}, {%8,%9}, {%0,%1,%2,%3};"              \
        : "+r"((d)[0]), "+r"((d)[1]), "+r"((d)[2]), "+r"((d)[3])             \
        : "r"((a)[0]), "r"((a)[1]), "r"((a)[2]), "r"((a)[3]),                \
          "r"((b)[0]), "r"((b)[1]))

__device__ __forceinline__ uint32_t sw_off(uint32_t row, uint32_t kseg) {
    return row * 128 + ((kseg ^ (row & 7)) << 4);
}
__device__ __forceinline__ int8_t q8(float v, float inv) {
    int q = __float2int_rn(v * inv);
    q = max(-127, min(127, q));
    return (int8_t)q;
}

// ---------------- prep kernels ----------------
__global__ void reset_cnt() { if (threadIdx.x == 0 && blockIdx.x == 0) g_cnt = 0; }

__global__ void prep_x(const float4* __restrict__ x,
                       __nv_bfloat16* __restrict__ xh,
                       int8_t* __restrict__ xq)
{
    size_t i = (size_t)blockIdx.x * blockDim.x + threadIdx.x;
    float4 v = x[i];
    int r = (int)(i >> 7);
    int d = ((int)i & 127) * 4;
    __nv_bfloat16 h0 = __float2bfloat16(v.x), h1 = __float2bfloat16(v.y);
    __nv_bfloat16 h2 = __float2bfloat16(v.z), h3 = __float2bfloat16(v.w);
    __nv_bfloat162* hp = (__nv_bfloat162*)(xh + (size_t)r * KH1 + d);
    hp[0] = __nv_bfloat162(h0, h1);
    hp[1] = __nv_bfloat162(h2, h3);
    float l0 = v.x - __bfloat162float(h0), l1 = v.y - __bfloat162float(h1);
    float l2 = v.z - __bfloat162float(h2), l3 = v.w - __bfloat162float(h3);
    char4 ql = make_char4(q8(l0, IXL), q8(l1, IXL), q8(l2, IXL), q8(l3, IXL));
    char4 qx = make_char4(q8(v.x, IXH), q8(v.y, IXH), q8(v.z, IXH), q8(v.w, IXH));
    *(char4*)(xq + (size_t)r * KQ1 + d)       = ql;
    *(char4*)(xq + (size_t)r * KQ1 + 512 + d) = qx;
}
__global__ void prep_w1(const float* __restrict__ w,
                        __nv_bfloat16* __restrict__ wh,
                        int8_t* __restrict__ wq)
{
    size_t i = (size_t)blockIdx.x * blockDim.x + threadIdx.x;
    int r = (int)(i >> 9);
    int d = (int)(i & 511);
    float v = w[i];
    __nv_bfloat16 hb = __float2bfloat16(v);
    float hi = __bfloat162float(hb);
    wh[(size_t)r * KH1 + d] = hb;
    wq[(size_t)r * KQ1 + d]       = q8(hi, IWH);
    wq[(size_t)r * KQ1 + 512 + d] = q8(v - hi, IWL);
}
__global__ void pack_w2(const float* __restrict__ w, int8_t* __restrict__ o)
{
    size_t i = (size_t)blockIdx.x * blockDim.x + threadIdx.x;
    int r = (int)(i >> 11);
    int c = (int)(i & 2047);
    int v = (int)lrintf(w[i] * 4194304.0f);
    int a0 = ((v & 127) ^ 64) - 64;
    int v1 = (v - a0) >> 7;
    int a1 = ((v1 & 127) ^ 64) - 64;
    int a2 = (v1 - a1) >> 7;
    size_t base = (size_t)r * KB2;
    o[base + c]        = (int8_t)a2;
    o[base + 2048 + c] = (int8_t)a1;
    o[base + 4096 + c] = (int8_t)a0;
}

// ---------------- layer1: int8 cross + bf16 hi*hi + PLIF + flag ----------------
__global__ __launch_bounds__(256, 1)
void gemm_plif_l1(const int8_t* __restrict__ Aq, const int8_t* __restrict__ Bq,
                  const __nv_bfloat16* __restrict__ Ah,
                  const __nv_bfloat16* __restrict__ Bh,
                  const float* __restrict__ alphap,
                  int8_t* __restrict__ outp)
{
    extern __shared__ __align__(128) unsigned char smem_raw[];
    const uint32_t sbase = smem_u32(smem_raw);

    const int tid  = threadIdx.x;
    const int lane = tid & 31;
    const int wid  = tid >> 5;
    const int wm   = wid & 1;
    const int wn   = wid >> 1;
    const int sm_w = wm * 16;
    const int nn_w = wn * 32;

    const int bm0 = blockIdx.x * MS1;
    const int bn0 = blockIdx.y * TN1;

    const int a_row_l = lane & 15;
    const int a_ks_l  = lane >> 4;
    const int b_row_l = (lane & 7) + ((lane & 16) >> 1);
    const int b_ks_l  = (lane >> 3) & 1;

    // ---- phase 1: int8 cross terms, K=1024, 8 chunks of 128 ----
    auto loadq = [&](int cc, int buf) {
        const int col = cc * 128;
        #pragma unroll
        for (int i = tid; i < 1024; i += 256) {
            int kseg = i & 7, site = (i >> 3) & 31, t = i >> 8;
            const int8_t* g =
                Aq + ((size_t)t * BROWS + bm0 + site) * KQ1 + col + kseg * 16;
            CP_ASYNC16(sbase + buf * A1_STAGE + t * 4096 + sw_off(site, kseg), g);
        }
        #pragma unroll
        for (int i = tid; i < 1024; i += 256) {
            int kseg = i & 7, n = i >> 3;
            const int8_t* g =
                Bq + (size_t)(bn0 + n) * KQ1 + col + kseg * 16;
            CP_ASYNC16(sbase + SM1_B + buf * B1_STAGE + sw_off(n, kseg), g);
        }
        CP_COMMIT();
    };

    float accf[TT][4][4];
    {
        int acci[TT][4][4];
        #pragma unroll
        for (int t = 0; t < TT; t++)
            #pragma unroll
            for (int n = 0; n < 4; n++)
                #pragma unroll
                for (int e = 0; e < 4; e++) acci[t][n][e] = 0;

        loadq(0, 0);
        loadq(1, 1);
        for (int cc = 0; cc < 8; cc++) {
            const int buf = cc % STG;
            if (cc < 7) asm volatile("cp.async.wait_group 1;" ::: "memory");
            else        asm volatile("cp.async.wait_group 0;" ::: "memory");
            __syncthreads();
            if (cc + 2 < 8) loadq(cc + 2, (cc + 2) % STG);

            #pragma unroll
            for (int ks = 0; ks < 4; ks++) {
                uint32_t b[4][2];
                #pragma unroll
                for (int p = 0; p < 2; p++) {
                    uint32_t addr = sbase + SM1_B + buf * B1_STAGE +
                        sw_off(nn_w + p * 16 + b_row_l, 2 * ks + b_ks_l);
                    LDSM_X4(b[2*p][0], b[2*p][1], b[2*p+1][0], b[2*p+1][1], addr);
                }
                uint32_t a[TT][4];
                #pragma unroll
                for (int t = 0; t < TT; t++) {
                    uint32_t addr = sbase + buf * A1_STAGE + t * 4096 +
                        sw_off(sm_w + a_row_l, 2 * ks + a_ks_l);
                    LDSM_X4(a[t][0], a[t][1], a[t][2], a[t][3], addr);
                }
                #pragma unroll
                for (int t = 0; t < TT; t++)
                    #pragma unroll
                    for (int n = 0; n < 4; n++)
                        IMMA16832(acci[t][n], a[t], b[n]);
            }
        }
        __syncthreads();
        #pragma unroll
        for (int t = 0; t < TT; t++)
            #pragma unroll
            for (int n = 0; n < 4; n++)
                #pragma unroll
                for (int e = 0; e < 4; e++)
                    accf[t][n][e] = CFOLD * (float)acci[t][n][e];
    }

    // ---- phase 2: bf16 hi*hi, K=512, 8 chunks of 64 ----
    auto loadh = [&](int cc, int buf) {
        const int col = cc * 64;
        #pragma unroll
        for (int i = tid; i < 1024; i += 256) {
            int kseg = i & 7, site = (i >> 3) & 31, t = i >> 8;
            const __nv_bfloat16* g =
                Ah + ((size_t)t * BROWS + bm0 + site) * KH1 + col + kseg * 8;
            CP_ASYNC16(sbase + buf * A1_STAGE + t * 4096 + sw_off(site, kseg), g);
        }
        #pragma unroll
        for (int i = tid; i < 1024; i += 256) {
            int kseg = i & 7, n = i >> 3;
            const __nv_bfloat16* g =
                Bh + (size_t)(bn0 + n) * KH1 + col + kseg * 8;
            CP_ASYNC16(sbase + SM1_B + buf * B1_STAGE + sw_off(n, kseg), g);
        }
        CP_COMMIT();
    };

    loadh(0, 0);
    loadh(1, 1);
    for (int cc = 0; cc < 8; cc++) {
        const int buf = cc % STG;
        if (cc < 7) asm volatile("cp.async.wait_group 1;" ::: "memory");
        else        asm volatile("cp.async.wait_group 0;" ::: "memory");
        __syncthreads();
        if (cc + 2 < 8) loadh(cc + 2, (cc + 2) % STG);

        #pragma unroll
        for (int ks = 0; ks < 4; ks++) {
            uint32_t b[4][2];
            #pragma unroll
            for (int p = 0; p < 2; p++) {
                uint32_t addr = sbase + SM1_B + buf * B1_STAGE +
                    sw_off(nn_w + p * 16 + b_row_l, 2 * ks + b_ks_l);
                LDSM_X4(b[2*p][0], b[2*p][1], b[2*p+1][0], b[2*p+1][1], addr);
            }
            uint32_t a[TT][4];
            #pragma unroll
            for (int t = 0; t < TT; t++) {
                uint32_t addr = sbase + buf * A1_STAGE + t * 4096 +
                    sw_off(sm_w + a_row_l, 2 * ks + a_ks_l);
                LDSM_X4(a[t][0], a[t][1], a[t][2], a[t][3], addr);
            }
            #pragma unroll
            for (int t = 0; t < TT; t++)
                #pragma unroll
                for (int n = 0; n < 4; n++)
                    MMA16816(accf[t][n], a[t], b[n]);
        }
    }

    // ---- light epilogue: scan, store spikes, flag tight margins ----
    const float alpha = alphap[0];
    const int row_in_m = lane >> 2;
    const int col_pair = (lane & 3) * 2;

    #pragma unroll
    for (int n = 0; n < 4; n++)
        #pragma unroll
        for (int rh = 0; rh < 2; rh++) {
            const int site = bm0 + sm_w + row_in_m + rh * 8;
            const int col  = bn0 + nn_w + n * 8 + col_pair;
            float v0 = 0.f, v1 = 0.f, m0 = 1e9f, m1 = 1e9f;
            #pragma unroll
            for (int t = 0; t < TT; t++) {
                v0 += alpha * (accf[t][n][rh * 2]     - v0);
                v1 += alpha * (accf[t][n][rh * 2 + 1] - v1);
                m0 = fminf(m0, fabsf(v0 - 1.0f));
                m1 = fminf(m1, fabsf(v1 - 1.0f));
                bool s0 = (v0 >= 1.0f), s1 = (v1 >= 1.0f);
                v0 = s0 ? 0.f : v0;
                v1 = s1 ? 0.f : v1;
                char2 pk;
                pk.x = s0 ? 1 : 0;
                pk.y = s1 ? 1 : 0;
                *(char2*)(outp + ((size_t)t * BROWS + site) * HH + col) = pk;
            }
            if (m0 < EPS) {
                int idx = atomicAdd(&g_cnt, 1);
                if (idx < LCAP) g_list[idx] = site * 2048 + col;
            }
            if (m1 < EPS) {
                int idx = atomicAdd(&g_cnt, 1);
                if (idx < LCAP) g_list[idx] = site * 2048 + col + 1;
            }
        }
}

// ---------------- repair: exact fp32 recompute of flagged neurons ----------------
__global__ void repair_l1(const float* __restrict__ xraw,
                          const float* __restrict__ w1raw,
                          const float* __restrict__ alphap,
                          int8_t* __restrict__ s1)
{
    const int total = min(g_cnt, LCAP);
    const float alpha = alphap[0];
    for (int i = blockIdx.x * blockDim.x + threadIdx.x; i < total;
         i += gridDim.x * blockDim.x) {
        const int e = g_list[i];
        const int site = e >> 11;
        const int neuron = e & 2047;
        const float4* wp = (const float4*)(w1raw + (size_t)neuron * 512);
        float v = 0.f;
        for (int t = 0; t < TT; t++) {
            const float4* xp = (const float4*)(xraw + ((size_t)t * BROWS + site) * 512);
            float a0 = 0.f, a1 = 0.f, a2 = 0.f, a3 = 0.f;
            #pragma unroll 4
            for (int k = 0; k < 128; k++) {
                float4 xv = xp[k], wv = wp[k];
                a0 += xv.x * wv.x; a1 += xv.y * wv.y;
                a2 += xv.z * wv.z; a3 += xv.w * wv.w;
            }
            float h = (a0 + a1) + (a2 + a3);
            v += alpha * (h - v);
            bool s = (v >= 1.0f);
            s1[((size_t)t * BROWS + site) * HH + neuron] = s ? 1 : 0;
            v = s ? 0.f : v;
        }
    }
}

// ---------------- layer2: int8 IMMA 3-digit exact + PLIF (R8-proven) ----------------
__global__ __launch_bounds__(256, 1)
void gemm_plif_l2(const int8_t* __restrict__ A,
                  const int8_t* __restrict__ Bw,
                  const float* __restrict__ alphap,
                  float* __restrict__ outp)
{
    extern __shared__ __align__(128) unsigned char smem_raw[];
    const uint32_t sbase = smem_u32(smem_raw);

    const int tid  = threadIdx.x;
    const int lane = tid & 31;
    const int wid  = tid >> 5;
    const int wm   = wid & 1;
    const int wn   = wid >> 1;
    const int sm_w = wm * 16;
    const int nn_w = wn * 32;

    const int bm0 = blockIdx.x * MS2;
    const int bn0 = blockIdx.y * TN2;
    const int NC  = KB2 / BK2;          // 48

    auto load_chunk = [&](int cc, int buf) {
        const int acol = (cc * BK2) % KA2;
        const int bcol = cc * BK2;
        #pragma unroll
        for (int i = tid; i < 1024; i += 256) {
            int kseg = i & 7, site = (i >> 3) & 31, t = i >> 8;
            const int8_t* g =
                A + ((size_t)t * BROWS + bm0 + site) * KA2 + acol + kseg * 16;
            CP_ASYNC16(sbase + buf * A2_STAGE + t * 4096 + sw_off(site, kseg), g);
        }
        #pragma unroll
        for (int i = tid; i < 1024; i += 256) {
            int kseg = i & 7, n = i >> 3;
            const int8_t* g =
                Bw + (size_t)(bn0 + n) * KB2 + bcol + kseg * 16;
            CP_ASYNC16(sbase + SM2_B + buf * B2_STAGE + sw_off(n, kseg), g);
        }
        CP_COMMIT();
    };

    int acc[TT][4][4];
    #pragma unroll
    for (int t = 0; t < TT; t++)
        #pragma unroll
        for (int n = 0; n < 4; n++)
            #pragma unroll
            for (int e = 0; e < 4; e++) acc[t][n][e] = 0;

    load_chunk(0, 0);
    load_chunk(1, 1);

    const int a_row_l = lane & 15;
    const int a_ks_l  = lane >> 4;
    const int b_row_l = (lane & 7) + ((lane & 16) >> 1);
    const int b_ks_l  = (lane >> 3) & 1;

    for (int cc = 0; cc < NC; cc++) {
        const int buf = cc % STG;
        if (cc < NC - 1) asm volatile("cp.async.wait_group 1;" ::: "memory");
        else             asm volatile("cp.async.wait_group 0;" ::: "memory");
        __syncthreads();
        if (cc + 2 < NC) load_chunk(cc + 2, (cc + 2) % STG);

        #pragma unroll
        for (int ks = 0; ks < 4; ks++) {
            uint32_t b[4][2];
            #pragma unroll
            for (int p = 0; p < 2; p++) {
                uint32_t addr = sbase + SM2_B + buf * B2_STAGE +
                    sw_off(nn_w + p * 16 + b_row_l, 2 * ks + b_ks_l);
                LDSM_X4(b[2*p][0], b[2*p][1], b[2*p+1][0], b[2*p+1][1], addr);
            }
            uint32_t a[TT][4];
            #pragma unroll
            for (int t = 0; t < TT; t++) {
                uint32_t addr = sbase + buf * A2_STAGE + t * 4096 +
                    sw_off(sm_w + a_row_l, 2 * ks + a_ks_l);
                LDSM_X4(a[t][0], a[t][1], a[t][2], a[t][3], addr);
            }
            #pragma unroll
            for (int t = 0; t < TT; t++)
                #pragma unroll
                for (int n = 0; n < 4; n++)
                    IMMA16832(acc[t][n], a[t], b[n]);
        }

        if (cc == 15 || cc == 31) {
            #pragma unroll
            for (int t = 0; t < TT; t++)
                #pragma unroll
                for (int n = 0; n < 4; n++)
                    #pragma unroll
                    for (int e = 0; e < 4; e++) acc[t][n][e] <<= 7;
        }
    }

    const float alpha = alphap[0];
    float sp_out[TT][4][4];
    #pragma unroll
    for (int n = 0; n < 4; n++)
        #pragma unroll
        for (int e = 0; e < 4; e++) {
            float v = 0.f;
            #pragma unroll
            for (int t = 0; t < TT; t++) {
                float y = (float)acc[t][n][e] * W2SCALE;
                v += alpha * (y - v);
                bool sp = (v >= 1.0f);
                sp_out[t][n][e] = sp ? 1.0f : 0.0f;
                v = sp ? 0.f : v;
            }
        }

    const int row_in_m = lane >> 2;
    const int col_pair = (lane & 3) * 2;
    #pragma unroll
    for (int t = 0; t < TT; t++)
        #pragma unroll
        for (int rh = 0; rh < 2; rh++) {
            int site = bm0 + sm_w + row_in_m + rh * 8;
            #pragma unroll
            for (int n = 0; n < 4; n++) {
                int col = bn0 + nn_w + n * 8 + col_pair;
                *(float2*)(outp + ((size_t)t * BROWS + site) * DD + col) =
                    make_float2(sp_out[t][n][rh * 2], sp_out[t][n][rh * 2 + 1]);
            }
        }
}

// ---------------- launch ----------------
extern "C" void kernel_launch(void* const* d_in, const int* in_sizes, int n_in,
                              void* d_out, int out_size)
{
    const float* x  = (const float*)d_in[0];
    const float* W1 = (const float*)d_in[1];
    const float* W2 = (const float*)d_in[2];
    const float* a1 = (const float*)d_in[3];
    const float* a2 = (const float*)d_in[4];
    float* out = (float*)d_out;

    __nv_bfloat16 *xh, *w1h;
    int8_t *xq, *w1q, *w2p, *s1;
    cudaGetSymbolAddress((void**)&xh,  g_xh);
    cudaGetSymbolAddress((void**)&xq,  g_xq);
    cudaGetSymbolAddress((void**)&w1h, g_w1h);
    cudaGetSymbolAddress((void**)&w1q, g_w1q);
    cudaGetSymbolAddress((void**)&w2p, g_w2);
    cudaGetSymbolAddress((void**)&s1,  g_s1);

    cudaFuncSetAttribute(gemm_plif_l1, cudaFuncAttributeMaxDynamicSharedMemorySize, SMEM1);
    cudaFuncSetAttribute(gemm_plif_l2, cudaFuncAttributeMaxDynamicSharedMemorySize, SMEM2);

    reset_cnt<<<1, 32>>>();
    prep_x<<<(TT * BROWS * DD / 4) / 256, 256>>>((const float4*)x, xh, xq);
    prep_w1<<<(HH * DD) / 256, 256>>>(W1, w1h, w1q);
    pack_w2<<<(DD * HH) / 256, 256>>>(W2, w2p);

    // layer 1: int8 cross (K=1024) + bf16 hi*hi (K=512) -> s1 + flags
    dim3 g1(BROWS / MS1, HH / TN1);   // 256 x 16
    gemm_plif_l1<<<g1, 256, SMEM1>>>(xq, w1q, xh, w1h, a1, s1);

    // repair flagged neurons exactly (fp32)
    repair_l1<<<512, 256>>>(x, W1, a1, s1);

    // layer 2: int8 IMMA 3-digit exact -> out fp32 spikes
    dim3 g2(BROWS / MS2, DD / TN2);   // 256 x 4
    gemm_plif_l2<<<g2, 256, SMEM2>>>(s1, w2p, a2, out);
}

// round 11
// speedup vs baseline: 2.5635x; 1.3504x over previous
#include <cuda_runtime.h>
#include <cuda_bf16.h>
#include <cstdint>
#include <cstddef>

// ---------------- problem dims ----------------
constexpr int TT    = 4;
constexpr int BROWS = 8192;
constexpr int DD    = 512;
constexpr int HH    = 2048;
constexpr int KQ1   = 1024;           // layer1 int8 K: [q(lo_x) | q(x)]
constexpr int KH1   = 512;            // layer1 bf16 K (hi*hi)
constexpr int KA2   = 2048;           // layer2 A cols (s1 int8, wraps)
constexpr int KB2   = 4096;           // layer2 K: 2 digit planes x 2048 int8

// layer1 quantization scales (bounds: |x|<8, |w1|<0.32)
constexpr float IXH = 127.0f / 8.0f;
constexpr float IXL = 512.0f * 127.0f / 8.0f;
constexpr float IWH = 127.0f / 0.32f;
constexpr float IWL = 512.0f * 127.0f / 0.32f;
constexpr float CFOLD = (float)((8.0 * 0.32) / (512.0 * 127.0 * 127.0));
constexpr float EPS1 = 5e-4f;         // ~10 sigma of l1 approx noise
// layer2: w2 fixed point at 2^15, 2 balanced base-128 digits (exact GEMM,
// only w2 quantization noise ~1e-5/weight)
constexpr float W2SCALE = 1.0f / 32768.0f;
constexpr float EPS2 = 4e-3f;         // ~10 sigma worst-case l2 noise

// ---- layer1 tile: CTA 32 x 128 x 4t, 8 warps of 16x32, 16 uniform chunks ----
constexpr int MS1 = 32, TN1 = 128, STG = 3;
constexpr uint32_t A1_STAGE = 16384;
constexpr uint32_t B1_STAGE = 16384;
constexpr uint32_t SM1_B = STG * A1_STAGE;
constexpr uint32_t SMEM1 = STG * (A1_STAGE + B1_STAGE);   // 98304

// ---- layer2 tile ----
constexpr int MS2 = 32, TN2 = 128, BK2 = 128;
constexpr uint32_t A2_STAGE = 16384;
constexpr uint32_t B2_STAGE = 16384;
constexpr uint32_t SM2_B = STG * A2_STAGE;
constexpr uint32_t SMEM2 = STG * (A2_STAGE + B2_STAGE);   // 98304

// ---------------- scratch ----------------
__device__ __nv_bfloat16 g_xh[(size_t)TT * BROWS * KH1];
__device__ int8_t        g_xq[(size_t)TT * BROWS * KQ1];
__device__ __nv_bfloat16 g_w1h[(size_t)HH * KH1];
__device__ int8_t        g_w1q[(size_t)HH * KQ1];
__device__ int8_t        g_w2[(size_t)DD * KB2];
__device__ int8_t        g_s1[(size_t)TT * BROWS * HH];
constexpr int LCAP = 1 << 22;
__device__ int g_cnt1, g_cnt2;
__device__ int g_list1[LCAP];
__device__ int g_list2[LCAP];

// ---------------- PTX helpers ----------------
__device__ __forceinline__ uint32_t smem_u32(const void* p) {
    uint32_t a;
    asm("{ .reg .u64 t; cvta.to.shared.u64 t, %1; cvt.u32.u64 %0, t; }" : "=r"(a) : "l"(p));
    return a;
}
#define CP_ASYNC16(dst, src) \
    asm volatile("cp.async.cg.shared.global [%0], [%1], 16;" :: "r"(dst), "l"(src) : "memory")
#define CP_COMMIT() asm volatile("cp.async.commit_group;" ::: "memory")

#define LDSM_X4(r0, r1, r2, r3, addr)                                        \
    asm volatile("ldmatrix.sync.aligned.m8n8.x4.shared.b16 {%0,%1,%2,%3}, [%4];" \
        : "=r"(r0), "=r"(r1), "=r"(r2), "=r"(r3) : "r"(addr))

#define MMA16816(d, a, b)                                                    \
    asm volatile("mma.sync.aligned.m16n8k16.row.col.f32.bf16.bf16.f32 "      \
        "{%0,%1,%2,%3}, {%4,%5,%6,%7}, {%8,%9}, {%0,%1,%2,%3};"              \
        : "+f"((d)[0]), "+f"((d)[1]), "+f"((d)[2]), "+f"((d)[3])             \
        : "r"((a)[0]), "r"((a)[1]), "r"((a)[2]), "r"((a)[3]),                \
          "r"((b)[0]), "r"((b)[1]))

#define IMMA16832(d, a, b)                                                   \
    asm volatile("mma.sync.aligned.m16n8k32.row.col.s32.s8.s8.s32 "          \
        "{%0,%1,%2,%3}, {%4,%5,%6,%7}, {%8,%9}, {%0,%1,%2,%3};"              \
        : "+r"((d)[0]), "+r"((d)[1]), "+r"((d)[2]), "+r"((d)[3])             \
        : "r"((a)[0]), "r"((a)[1]), "r"((a)[2]), "r"((a)[3]),                \
          "r"((b)[0]), "r"((b)[1]))

__device__ __forceinline__ uint32_t sw_off(uint32_t row, uint32_t kseg) {
    return row * 128 + ((kseg ^ (row & 7)) << 4);
}
__device__ __forceinline__ int8_t q8(float v, float inv) {
    int q = __float2int_rn(v * inv);
    q = max(-127, min(127, q));
    return (int8_t)q;
}

// ---------------- prep kernels ----------------
__global__ void reset_cnt() {
    if (threadIdx.x == 0 && blockIdx.x == 0) { g_cnt1 = 0; g_cnt2 = 0; }
}
__global__ void prep_x(const float4* __restrict__ x,
                       __nv_bfloat16* __restrict__ xh,
                       int8_t* __restrict__ xq)
{
    size_t i = (size_t)blockIdx.x * blockDim.x + threadIdx.x;
    float4 v = x[i];
    int r = (int)(i >> 7);
    int d = ((int)i & 127) * 4;
    __nv_bfloat16 h0 = __float2bfloat16(v.x), h1 = __float2bfloat16(v.y);
    __nv_bfloat16 h2 = __float2bfloat16(v.z), h3 = __float2bfloat16(v.w);
    __nv_bfloat162* hp = (__nv_bfloat162*)(xh + (size_t)r * KH1 + d);
    hp[0] = __nv_bfloat162(h0, h1);
    hp[1] = __nv_bfloat162(h2, h3);
    float l0 = v.x - __bfloat162float(h0), l1 = v.y - __bfloat162float(h1);
    float l2 = v.z - __bfloat162float(h2), l3 = v.w - __bfloat162float(h3);
    char4 ql = make_char4(q8(l0, IXL), q8(l1, IXL), q8(l2, IXL), q8(l3, IXL));
    char4 qx = make_char4(q8(v.x, IXH), q8(v.y, IXH), q8(v.z, IXH), q8(v.w, IXH));
    *(char4*)(xq + (size_t)r * KQ1 + d)       = ql;
    *(char4*)(xq + (size_t)r * KQ1 + 512 + d) = qx;
}
__global__ void prep_w1(const float* __restrict__ w,
                        __nv_bfloat16* __restrict__ wh,
                        int8_t* __restrict__ wq)
{
    size_t i = (size_t)blockIdx.x * blockDim.x + threadIdx.x;
    int r = (int)(i >> 9);
    int d = (int)(i & 511);
    float v = w[i];
    __nv_bfloat16 hb = __float2bfloat16(v);
    float hi = __bfloat162float(hb);
    wh[(size_t)r * KH1 + d] = hb;
    wq[(size_t)r * KQ1 + d]       = q8(hi, IWH);
    wq[(size_t)r * KQ1 + 512 + d] = q8(v - hi, IWL);
}
// W2 -> 2 balanced base-128 digit planes at scale 2^15: [d1 | d0]
__global__ void pack_w2(const float* __restrict__ w, int8_t* __restrict__ o)
{
    size_t i = (size_t)blockIdx.x * blockDim.x + threadIdx.x;
    int r = (int)(i >> 11);
    int c = (int)(i & 2047);
    int v = (int)lrintf(w[i] * 32768.0f);
    v = max(-8192, min(8192, v));
    int d0 = ((v & 127) ^ 64) - 64;
    int d1 = (v - d0) >> 7;
    size_t base = (size_t)r * KB2;
    o[base + c]        = (int8_t)d1;
    o[base + 2048 + c] = (int8_t)d0;
}

// ---------------- layer1: unified int8+bf16 pipeline, PLIF, flag ----------------
// Both A arrays have 1024-byte rows; all 16 chunks are 128-byte columns.
__global__ __launch_bounds__(256, 1)
void gemm_plif_l1(const void* __restrict__ Aq, const void* __restrict__ Bq,
                  const void* __restrict__ Ah, const void* __restrict__ Bh,
                  const float* __restrict__ alphap,
                  int8_t* __restrict__ outp)
{
    extern __shared__ __align__(128) unsigned char smem_raw[];
    const uint32_t sbase = smem_u32(smem_raw);

    const int tid  = threadIdx.x;
    const int lane = tid & 31;
    const int wid  = tid >> 5;
    const int wm   = wid & 1;
    const int wn   = wid >> 1;
    const int sm_w = wm * 16;
    const int nn_w = wn * 32;

    const int bm0 = blockIdx.x * MS1;
    const int bn0 = blockIdx.y * TN1;

    const int a_row_l = lane & 15;
    const int a_ks_l  = lane >> 4;
    const int b_row_l = (lane & 7) + ((lane & 16) >> 1);
    const int b_ks_l  = (lane >> 3) & 1;

    // uniform byte-addressed loader; chunks 0-7 int8, 8-15 bf16
    auto load_chunk = [&](int cc, int buf) {
        const char* Ab = (const char*)((cc < 8) ? Aq : Ah);
        const char* Bb = (const char*)((cc < 8) ? Bq : Bh);
        const int bcol = (cc & 7) * 128;
        #pragma unroll
        for (int i = tid; i < 1024; i += 256) {
            int kseg = i & 7, site = (i >> 3) & 31, t = i >> 8;
            const char* g = Ab + ((size_t)t * BROWS + bm0 + site) * 1024
                               + bcol + kseg * 16;
            CP_ASYNC16(sbase + buf * A1_STAGE + t * 4096 + sw_off(site, kseg), g);
        }
        #pragma unroll
        for (int i = tid; i < 1024; i += 256) {
            int kseg = i & 7, n = i >> 3;
            const char* g = Bb + (size_t)(bn0 + n) * 1024 + bcol + kseg * 16;
            CP_ASYNC16(sbase + SM1_B + buf * B1_STAGE + sw_off(n, kseg), g);
        }
        CP_COMMIT();
    };

    float accf[TT][4][4];
    load_chunk(0, 0);
    load_chunk(1, 1);

    {   // ---- int8 phase: chunks 0-7 (pipeline continues into bf16 chunks) ----
        int acci[TT][4][4];
        #pragma unroll
        for (int t = 0; t < TT; t++)
            #pragma unroll
            for (int n = 0; n < 4; n++)
                #pragma unroll
                for (int e = 0; e < 4; e++) acci[t][n][e] = 0;

        for (int cc = 0; cc < 8; cc++) {
            const int buf = cc % STG;
            asm volatile("cp.async.wait_group 1;" ::: "memory");
            __syncthreads();
            load_chunk(cc + 2, (cc + 2) % STG);   // cc=6,7 prefetch bf16 chunks

            #pragma unroll
            for (int ks = 0; ks < 4; ks++) {
                uint32_t b[4][2];
                #pragma unroll
                for (int p = 0; p < 2; p++) {
                    uint32_t addr = sbase + SM1_B + buf * B1_STAGE +
                        sw_off(nn_w + p * 16 + b_row_l, 2 * ks + b_ks_l);
                    LDSM_X4(b[2*p][0], b[2*p][1], b[2*p+1][0], b[2*p+1][1], addr);
                }
                uint32_t a[TT][4];
                #pragma unroll
                for (int t = 0; t < TT; t++) {
                    uint32_t addr = sbase + buf * A1_STAGE + t * 4096 +
                        sw_off(sm_w + a_row_l, 2 * ks + a_ks_l);
                    LDSM_X4(a[t][0], a[t][1], a[t][2], a[t][3], addr);
                }
                #pragma unroll
                for (int t = 0; t < TT; t++)
                    #pragma unroll
                    for (int n = 0; n < 4; n++)
                        IMMA16832(acci[t][n], a[t], b[n]);
            }
        }
        #pragma unroll
        for (int t = 0; t < TT; t++)
            #pragma unroll
            for (int n = 0; n < 4; n++)
                #pragma unroll
                for (int e = 0; e < 4; e++)
                    accf[t][n][e] = CFOLD * (float)acci[t][n][e];
    }

    // ---- bf16 phase: chunks 8-15, same ring, no drain ----
    for (int cc = 8; cc < 16; cc++) {
        const int buf = cc % STG;
        if (cc < 15) asm volatile("cp.async.wait_group 1;" ::: "memory");
        else         asm volatile("cp.async.wait_group 0;" ::: "memory");
        __syncthreads();
        if (cc + 2 < 16) load_chunk(cc + 2, (cc + 2) % STG);

        #pragma unroll
        for (int ks = 0; ks < 4; ks++) {
            uint32_t b[4][2];
            #pragma unroll
            for (int p = 0; p < 2; p++) {
                uint32_t addr = sbase + SM1_B + buf * B1_STAGE +
                    sw_off(nn_w + p * 16 + b_row_l, 2 * ks + b_ks_l);
                LDSM_X4(b[2*p][0], b[2*p][1], b[2*p+1][0], b[2*p+1][1], addr);
            }
            uint32_t a[TT][4];
            #pragma unroll
            for (int t = 0; t < TT; t++) {
                uint32_t addr = sbase + buf * A1_STAGE + t * 4096 +
                    sw_off(sm_w + a_row_l, 2 * ks + a_ks_l);
                LDSM_X4(a[t][0], a[t][1], a[t][2], a[t][3], addr);
            }
            #pragma unroll
            for (int t = 0; t < TT; t++)
                #pragma unroll
                for (int n = 0; n < 4; n++)
                    MMA16816(accf[t][n], a[t], b[n]);
        }
    }

    // ---- epilogue: scan, store spikes, flag tight margins ----
    const float alpha = alphap[0];
    const int row_in_m = lane >> 2;
    const int col_pair = (lane & 3) * 2;

    #pragma unroll
    for (int n = 0; n < 4; n++)
        #pragma unroll
        for (int rh = 0; rh < 2; rh++) {
            const int site = bm0 + sm_w + row_in_m + rh * 8;
            const int col  = bn0 + nn_w + n * 8 + col_pair;
            float v0 = 0.f, v1 = 0.f, m0 = 1e9f, m1 = 1e9f;
            #pragma unroll
            for (int t = 0; t < TT; t++) {
                v0 += alpha * (accf[t][n][rh * 2]     - v0);
                v1 += alpha * (accf[t][n][rh * 2 + 1] - v1);
                m0 = fminf(m0, fabsf(v0 - 1.0f));
                m1 = fminf(m1, fabsf(v1 - 1.0f));
                bool s0 = (v0 >= 1.0f), s1 = (v1 >= 1.0f);
                v0 = s0 ? 0.f : v0;
                v1 = s1 ? 0.f : v1;
                char2 pk;
                pk.x = s0 ? 1 : 0;
                pk.y = s1 ? 1 : 0;
                *(char2*)(outp + ((size_t)t * BROWS + site) * HH + col) = pk;
            }
            if (m0 < EPS1) {
                int idx = atomicAdd(&g_cnt1, 1);
                if (idx < LCAP) g_list1[idx] = site * 2048 + col;
            }
            if (m1 < EPS1) {
                int idx = atomicAdd(&g_cnt1, 1);
                if (idx < LCAP) g_list1[idx] = site * 2048 + col + 1;
            }
        }
}

// ---------------- repair1: warp-per-neuron exact fp32 recompute ----------------
__global__ void repair_l1(const float* __restrict__ xraw,
                          const float* __restrict__ w1raw,
                          const float* __restrict__ alphap,
                          int8_t* __restrict__ s1)
{
    const int total = min(g_cnt1, LCAP);
    const float alpha = alphap[0];
    const int lane = threadIdx.x & 31;
    const int nwarp = (gridDim.x * blockDim.x) >> 5;
    for (int w = (blockIdx.x * blockDim.x + threadIdx.x) >> 5; w < total; w += nwarp) {
        const int e = g_list1[w];
        const int site = e >> 11, neuron = e & 2047;
        const float4* wp = (const float4*)(w1raw + (size_t)neuron * 512);
        float v = 0.f;
        for (int t = 0; t < TT; t++) {
            const float4* xp = (const float4*)(xraw + ((size_t)t * BROWS + site) * 512);
            float p = 0.f;
            #pragma unroll
            for (int k = 0; k < 4; k++) {
                float4 xv = xp[lane + k * 32], wv = wp[lane + k * 32];
                p += xv.x * wv.x + xv.y * wv.y + xv.z * wv.z + xv.w * wv.w;
            }
            #pragma unroll
            for (int o = 16; o; o >>= 1) p += __shfl_xor_sync(0xFFFFFFFF, p, o);
            v += alpha * (p - v);
            bool s = (v >= 1.0f);
            if (lane == 0)
                s1[((size_t)t * BROWS + site) * HH + neuron] = s ? 1 : 0;
            v = s ? 0.f : v;
        }
    }
}

// ---------------- layer2: int8 IMMA 2-digit + PLIF + flag ----------------
__global__ __launch_bounds__(256, 1)
void gemm_plif_l2(const int8_t* __restrict__ A,
                  const int8_t* __restrict__ Bw,
                  const float* __restrict__ alphap,
                  float* __restrict__ outp)
{
    extern __shared__ __align__(128) unsigned char smem_raw[];
    const uint32_t sbase = smem_u32(smem_raw);

    const int tid  = threadIdx.x;
    const int lane = tid & 31;
    const int wid  = tid >> 5;
    const int wm   = wid & 1;
    const int wn   = wid >> 1;
    const int sm_w = wm * 16;
    const int nn_w = wn * 32;

    const int bm0 = blockIdx.x * MS2;
    const int bn0 = blockIdx.y * TN2;
    const int NC  = KB2 / BK2;          // 32; digit fold at cc==15

    auto load_chunk = [&](int cc, int buf) {
        const int acol = (cc * BK2) % KA2;
        const int bcol = cc * BK2;
        #pragma unroll
        for (int i = tid; i < 1024; i += 256) {
            int kseg = i & 7, site = (i >> 3) & 31, t = i >> 8;
            const int8_t* g =
                A + ((size_t)t * BROWS + bm0 + site) * KA2 + acol + kseg * 16;
            CP_ASYNC16(sbase + buf * A2_STAGE + t * 4096 + sw_off(site, kseg), g);
        }
        #pragma unroll
        for (int i = tid; i < 1024; i += 256) {
            int kseg = i & 7, n = i >> 3;
            const int8_t* g =
                Bw + (size_t)(bn0 + n) * KB2 + bcol + kseg * 16;
            CP_ASYNC16(sbase + SM2_B + buf * B2_STAGE + sw_off(n, kseg), g);
        }
        CP_COMMIT();
    };

    int acc[TT][4][4];
    #pragma unroll
    for (int t = 0; t < TT; t++)
        #pragma unroll
        for (int n = 0; n < 4; n++)
            #pragma unroll
            for (int e = 0; e < 4; e++) acc[t][n][e] = 0;

    load_chunk(0, 0);
    load_chunk(1, 1);

    const int a_row_l = lane & 15;
    const int a_ks_l  = lane >> 4;
    const int b_row_l = (lane & 7) + ((lane & 16) >> 1);
    const int b_ks_l  = (lane >> 3) & 1;

    for (int cc = 0; cc < NC; cc++) {
        const int buf = cc % STG;
        if (cc < NC - 1) asm volatile("cp.async.wait_group 1;" ::: "memory");
        else             asm volatile("cp.async.wait_group 0;" ::: "memory");
        __syncthreads();
        if (cc + 2 < NC) load_chunk(cc + 2, (cc + 2) % STG);

        #pragma unroll
        for (int ks = 0; ks < 4; ks++) {
            uint32_t b[4][2];
            #pragma unroll
            for (int p = 0; p < 2; p++) {
                uint32_t addr = sbase + SM2_B + buf * B2_STAGE +
                    sw_off(nn_w + p * 16 + b_row_l, 2 * ks + b_ks_l);
                LDSM_X4(b[2*p][0], b[2*p][1], b[2*p+1][0], b[2*p+1][1], addr);
            }
            uint32_t a[TT][4];
            #pragma unroll
            for (int t = 0; t < TT; t++) {
                uint32_t addr = sbase + buf * A2_STAGE + t * 4096 +
                    sw_off(sm_w + a_row_l, 2 * ks + a_ks_l);
                LDSM_X4(a[t][0], a[t][1], a[t][2], a[t][3], addr);
            }
            #pragma unroll
            for (int t = 0; t < TT; t++)
                #pragma unroll
                for (int n = 0; n < 4; n++)
                    IMMA16832(acc[t][n], a[t], b[n]);
        }

        if (cc == 15) {                 // exact digit fold (d1 plane done)
            #pragma unroll
            for (int t = 0; t < TT; t++)
                #pragma unroll
                for (int n = 0; n < 4; n++)
                    #pragma unroll
                    for (int e = 0; e < 4; e++) acc[t][n][e] <<= 7;
        }
    }

    // PLIF scan on y = acc * 2^-15, store spikes, flag tight margins
    const float alpha = alphap[0];
    const int row_in_m = lane >> 2;
    const int col_pair = (lane & 3) * 2;
    #pragma unroll
    for (int n = 0; n < 4; n++)
        #pragma unroll
        for (int rh = 0; rh < 2; rh++) {
            const int site = bm0 + sm_w + row_in_m + rh * 8;
            const int col  = bn0 + nn_w + n * 8 + col_pair;
            float v0 = 0.f, v1 = 0.f, m0 = 1e9f, m1 = 1e9f;
            #pragma unroll
            for (int t = 0; t < TT; t++) {
                float y0 = (float)acc[t][n][rh * 2]     * W2SCALE;
                float y1 = (float)acc[t][n][rh * 2 + 1] * W2SCALE;
                v0 += alpha * (y0 - v0);
                v1 += alpha * (y1 - v1);
                m0 = fminf(m0, fabsf(v0 - 1.0f));
                m1 = fminf(m1, fabsf(v1 - 1.0f));
                bool s0 = (v0 >= 1.0f), s1v = (v1 >= 1.0f);
                v0 = s0 ? 0.f : v0;
                v1 = s1v ? 0.f : v1;
                *(float2*)(outp + ((size_t)t * BROWS + site) * DD + col) =
                    make_float2(s0 ? 1.0f : 0.0f, s1v ? 1.0f : 0.0f);
            }
            if (m0 < EPS2) {
                int idx = atomicAdd(&g_cnt2, 1);
                if (idx < LCAP) g_list2[idx] = site * 512 + col;
            }
            if (m1 < EPS2) {
                int idx = atomicAdd(&g_cnt2, 1);
                if (idx < LCAP) g_list2[idx] = site * 512 + col + 1;
            }
        }
}

// ---------------- repair2: warp-per-neuron exact recompute of out ----------------
__global__ void repair_l2(const int8_t* __restrict__ s1,
                          const float* __restrict__ w2raw,
                          const float* __restrict__ alphap,
                          float* __restrict__ outp)
{
    const int total = min(g_cnt2, LCAP);
    const float alpha = alphap[0];
    const int lane = threadIdx.x & 31;
    const int nwarp = (gridDim.x * blockDim.x) >> 5;
    for (int w = (blockIdx.x * blockDim.x + threadIdx.x) >> 5; w < total; w += nwarp) {
        const int e = g_list2[w];
        const int site = e >> 9, col = e & 511;
        const float4* wp = (const float4*)(w2raw + (size_t)col * 2048);
        float v = 0.f;
        for (int t = 0; t < TT; t++) {
            const char4* sp = (const char4*)(s1 + ((size_t)t * BROWS + site) * HH);
            float p = 0.f;
            #pragma unroll
            for (int k = 0; k < 16; k++) {
                char4 sv = sp[lane + k * 32];
                float4 wv = wp[lane + k * 32];
                if (sv.x) p += wv.x;
                if (sv.y) p += wv.y;
                if (sv.z) p += wv.z;
                if (sv.w) p += wv.w;
            }
            #pragma unroll
            for (int o = 16; o; o >>= 1) p += __shfl_xor_sync(0xFFFFFFFF, p, o);
            v += alpha * (p - v);
            bool s = (v >= 1.0f);
            if (lane == 0)
                outp[((size_t)t * BROWS + site) * DD + col] = s ? 1.0f : 0.0f;
            v = s ? 0.f : v;
        }
    }
}

// ---------------- launch ----------------
extern "C" void kernel_launch(void* const* d_in, const int* in_sizes, int n_in,
                              void* d_out, int out_size)
{
    const float* x  = (const float*)d_in[0];
    const float* W1 = (const float*)d_in[1];
    const float* W2 = (const float*)d_in[2];
    const float* a1 = (const float*)d_in[3];
    const float* a2 = (const float*)d_in[4];
    float* out = (float*)d_out;

    __nv_bfloat16 *xh, *w1h;
    int8_t *xq, *w1q, *w2p, *s1;
    cudaGetSymbolAddress((void**)&xh,  g_xh);
    cudaGetSymbolAddress((void**)&xq,  g_xq);
    cudaGetSymbolAddress((void**)&w1h, g_w1h);
    cudaGetSymbolAddress((void**)&w1q, g_w1q);
    cudaGetSymbolAddress((void**)&w2p, g_w2);
    cudaGetSymbolAddress((void**)&s1,  g_s1);

    cudaFuncSetAttribute(gemm_plif_l1, cudaFuncAttributeMaxDynamicSharedMemorySize, SMEM1);
    cudaFuncSetAttribute(gemm_plif_l2, cudaFuncAttributeMaxDynamicSharedMemorySize, SMEM2);

    reset_cnt<<<1, 32>>>();
    prep_x<<<(TT * BROWS * DD / 4) / 256, 256>>>((const float4*)x, xh, xq);
    prep_w1<<<(HH * DD) / 256, 256>>>(W1, w1h, w1q);
    pack_w2<<<(DD * HH) / 256, 256>>>(W2, w2p);

    // layer 1: unified int8 cross (K=1024) + bf16 hi*hi (K=512) -> s1 + flags
    dim3 g1(BROWS / MS1, HH / TN1);   // 256 x 16
    gemm_plif_l1<<<g1, 256, SMEM1>>>(xq, w1q, xh, w1h, a1, s1);
    repair_l1<<<512, 256>>>(x, W1, a1, s1);

    // layer 2: int8 IMMA 2-digit (K=4096) -> out + flags
    dim3 g2(BROWS / MS2, DD / TN2);   // 256 x 4
    gemm_plif_l2<<<g2, 256, SMEM2>>>(s1, w2p, a2, out);
    repair_l2<<<512, 256>>>(s1, W2, a2, out);
}

// round 12
// speedup vs baseline: 2.7372x; 1.0678x over previous
#include <cuda_runtime.h>
#include <cuda_bf16.h>
#include <cuda_fp16.h>
#include <cstdint>
#include <cstddef>

// ---------------- problem dims ----------------
constexpr int TT    = 4;
constexpr int BROWS = 8192;
constexpr int DD    = 512;
constexpr int HH    = 2048;
constexpr int KQ1   = 1024;           // layer1 int8 K: [q(lx) | q(x)]
constexpr int KH1   = 512;            // layer1 fp16 K (hi*hi)
constexpr int KA2   = 2048;           // layer2 A cols (s1 int8, wraps)
constexpr int KB2   = 4096;           // layer2 K: 2 digit planes x 2048 int8

// layer1 scales. fp16 split: |lx| <= 2^-9, |lw| <= 2^-13.
// Fold constraint (one int8 GEMM): 1/(IXL*IWH) == 1/(IXH*IWL); exact here:
// 0.32/40000 == 8/1e6.
constexpr float IXH = 127.0f / 8.0f;
constexpr float IXL = 40000.0f;            // q(lx) max ~78
constexpr float IWH = 127.0f / 0.32f;
constexpr float IWL = 1000000.0f;          // q(lw) max ~122
constexpr float CFOLD = 8.0f / (127.0f * 1000000.0f);   // 6.2992e-8
constexpr float EPS1 = 2.5e-4f;            // ~18 sigma of l1 approx noise
constexpr float W2SCALE = 1.0f / 32768.0f; // layer2 2-digit fixed point
constexpr float EPS2 = 4e-3f;              // proven in R11

// ---- layer1 tile: CTA 32 x 128 x 4t, 8 warps of 16x32, 16 uniform chunks ----
constexpr int MS1 = 32, TN1 = 128, STG = 4;
constexpr uint32_t A1_STAGE = 16384;
constexpr uint32_t B1_STAGE = 16384;
constexpr uint32_t SM1_B = STG * A1_STAGE;
constexpr uint32_t SMEM1 = STG * (A1_STAGE + B1_STAGE);   // 131072

// ---- layer2 tile ----
constexpr int MS2 = 32, TN2 = 128, BK2 = 128;
constexpr uint32_t A2_STAGE = 16384;
constexpr uint32_t B2_STAGE = 16384;
constexpr uint32_t SM2_B = STG * A2_STAGE;
constexpr uint32_t SMEM2 = STG * (A2_STAGE + B2_STAGE);   // 131072

// ---------------- scratch ----------------
__device__ __half  g_xh[(size_t)TT * BROWS * KH1];   // fp16(x)
__device__ int8_t  g_xq[(size_t)TT * BROWS * KQ1];   // [q(lx)|q(x)]
__device__ __half  g_w1h[(size_t)HH * KH1];          // fp16(w1)
__device__ int8_t  g_w1q[(size_t)HH * KQ1];          // [q(hw)|q(lw)]
__device__ int8_t  g_w2[(size_t)DD * KB2];           // 2 digit planes
__device__ int8_t  g_s1[(size_t)TT * BROWS * HH];
constexpr int LCAP = 1 << 22;
__device__ int g_cnt1, g_cnt2;
__device__ int g_list1[LCAP];
__device__ int g_list2[LCAP];

// ---------------- PTX helpers ----------------
__device__ __forceinline__ uint32_t smem_u32(const void* p) {
    uint32_t a;
    asm("{ .reg .u64 t; cvta.to.shared.u64 t, %1; cvt.u32.u64 %0, t; }" : "=r"(a) : "l"(p));
    return a;
}
#define CP_ASYNC16(dst, src) \
    asm volatile("cp.async.cg.shared.global [%0], [%1], 16;" :: "r"(dst), "l"(src) : "memory")
#define CP_COMMIT() asm volatile("cp.async.commit_group;" ::: "memory")

#define LDSM_X4(r0, r1, r2, r3, addr)                                        \
    asm volatile("ldmatrix.sync.aligned.m8n8.x4.shared.b16 {%0,%1,%2,%3}, [%4];" \
        : "=r"(r0), "=r"(r1), "=r"(r2), "=r"(r3) : "r"(addr))

#define MMAF16(d, a, b)                                                      \
    asm volatile("mma.sync.aligned.m16n8k16.row.col.f32.f16.f16.f32 "        \
        "{%0,%1,%2,%3}, {%4,%5,%6,%7}, {%8,%9}, {%0,%1,%2,%3};"              \
        : "+f"((d)[0]), "+f"((d)[1]), "+f"((d)[2]), "+f"((d)[3])             \
        : "r"((a)[0]), "r"((a)[1]), "r"((a)[2]), "r"((a)[3]),                \
          "r"((b)[0]), "r"((b)[1]))

#define IMMA16832(d, a, b)                                                   \
    asm volatile("mma.sync.aligned.m16n8k32.row.col.s32.s8.s8.s32 "          \
        "{%0,%1,%2,%3}, {%4,%5,%6,%7}, {%8,%9}, {%0,%1,%2,%3};"              \
        : "+r"((d)[0]), "+r"((d)[1]), "+r"((d)[2]), "+r"((d)[3])             \
        : "r"((a)[0]), "r"((a)[1]), "r"((a)[2]), "r"((a)[3]),                \
          "r"((b)[0]), "r"((b)[1]))

__device__ __forceinline__ uint32_t sw_off(uint32_t row, uint32_t kseg) {
    return row * 128 + ((kseg ^ (row & 7)) << 4);
}
__device__ __forceinline__ int8_t q8(float v, float inv) {
    int q = __float2int_rn(v * inv);
    q = max(-127, min(127, q));
    return (int8_t)q;
}

// ---------------- prep kernels ----------------
__global__ void prep_x(const float4* __restrict__ x,
                       __half* __restrict__ xh,
                       int8_t* __restrict__ xq)
{
    if (blockIdx.x == 0 && threadIdx.x == 0) { g_cnt1 = 0; g_cnt2 = 0; }
    size_t i = (size_t)blockIdx.x * blockDim.x + threadIdx.x;
    float4 v = x[i];
    int r = (int)(i >> 7);
    int d = ((int)i & 127) * 4;
    __half h0 = __float2half_rn(v.x), h1 = __float2half_rn(v.y);
    __half h2 = __float2half_rn(v.z), h3 = __float2half_rn(v.w);
    __half2* hp = (__half2*)(xh + (size_t)r * KH1 + d);
    hp[0] = __halves2half2(h0, h1);
    hp[1] = __halves2half2(h2, h3);
    float l0 = v.x - __half2float(h0), l1 = v.y - __half2float(h1);
    float l2 = v.z - __half2float(h2), l3 = v.w - __half2float(h3);
    char4 ql = make_char4(q8(l0, IXL), q8(l1, IXL), q8(l2, IXL), q8(l3, IXL));
    char4 qx = make_char4(q8(v.x, IXH), q8(v.y, IXH), q8(v.z, IXH), q8(v.w, IXH));
    *(char4*)(xq + (size_t)r * KQ1 + d)       = ql;
    *(char4*)(xq + (size_t)r * KQ1 + 512 + d) = qx;
}
__global__ void prep_w1(const float* __restrict__ w,
                        __half* __restrict__ wh,
                        int8_t* __restrict__ wq)
{
    size_t i = (size_t)blockIdx.x * blockDim.x + threadIdx.x;
    int r = (int)(i >> 9);
    int d = (int)(i & 511);
    float v = w[i];
    __half hb = __float2half_rn(v);
    float hi = __half2float(hb);
    wh[(size_t)r * KH1 + d] = hb;
    wq[(size_t)r * KQ1 + d]       = q8(hi, IWH);
    wq[(size_t)r * KQ1 + 512 + d] = q8(v - hi, IWL);
}
__global__ void pack_w2(const float* __restrict__ w, int8_t* __restrict__ o)
{
    size_t i = (size_t)blockIdx.x * blockDim.x + threadIdx.x;
    int r = (int)(i >> 11);
    int c = (int)(i & 2047);
    int v = (int)lrintf(w[i] * 32768.0f);
    v = max(-8192, min(8192, v));
    int d0 = ((v & 127) ^ 64) - 64;
    int d1 = (v - d0) >> 7;
    size_t base = (size_t)r * KB2;
    o[base + c]        = (int8_t)d1;
    o[base + 2048 + c] = (int8_t)d0;
}

// ---------------- layer1: unified int8+fp16 pipeline, PLIF, flag ----------------
__global__ __launch_bounds__(256, 1)
void gemm_plif_l1(const void* __restrict__ Aq, const void* __restrict__ Bq,
                  const void* __restrict__ Ah, const void* __restrict__ Bh,
                  const float* __restrict__ alphap,
                  int8_t* __restrict__ outp)
{
    extern __shared__ __align__(128) unsigned char smem_raw[];
    const uint32_t sbase = smem_u32(smem_raw);

    const int tid  = threadIdx.x;
    const int lane = tid & 31;
    const int wid  = tid >> 5;
    const int wm   = wid & 1;
    const int wn   = wid >> 1;
    const int sm_w = wm * 16;
    const int nn_w = wn * 32;

    const int bm0 = blockIdx.x * MS1;
    const int bn0 = blockIdx.y * TN1;

    const int a_row_l = lane & 15;
    const int a_ks_l  = lane >> 4;
    const int b_row_l = (lane & 7) + ((lane & 16) >> 1);
    const int b_ks_l  = (lane >> 3) & 1;

    // uniform loader; chunks 0-7 int8, 8-15 fp16 (both 1024B rows)
    auto load_chunk = [&](int cc, int buf) {
        const char* Ab = (const char*)((cc < 8) ? Aq : Ah);
        const char* Bb = (const char*)((cc < 8) ? Bq : Bh);
        const int bcol = (cc & 7) * 128;
        #pragma unroll
        for (int i = tid; i < 1024; i += 256) {
            int kseg = i & 7, site = (i >> 3) & 31, t = i >> 8;
            const char* g = Ab + ((size_t)t * BROWS + bm0 + site) * 1024
                               + bcol + kseg * 16;
            CP_ASYNC16(sbase + buf * A1_STAGE + t * 4096 + sw_off(site, kseg), g);
        }
        #pragma unroll
        for (int i = tid; i < 1024; i += 256) {
            int kseg = i & 7, n = i >> 3;
            const char* g = Bb + (size_t)(bn0 + n) * 1024 + bcol + kseg * 16;
            CP_ASYNC16(sbase + SM1_B + buf * B1_STAGE + sw_off(n, kseg), g);
        }
        CP_COMMIT();
    };

    float accf[TT][4][4];
    load_chunk(0, 0);
    load_chunk(1, 1);

    {   // ---- int8 phase: chunks 0-7 ----
        int acci[TT][4][4];
        #pragma unroll
        for (int t = 0; t < TT; t++)
            #pragma unroll
            for (int n = 0; n < 4; n++)
                #pragma unroll
                for (int e = 0; e < 4; e++) acci[t][n][e] = 0;

        for (int cc = 0; cc < 8; cc++) {
            const int buf = cc & (STG - 1);
            load_chunk(cc + 2, (cc + 2) & (STG - 1));   // early issue (safe: STG=4)
            asm volatile("cp.async.wait_group 2;" ::: "memory");
            __syncthreads();

            #pragma unroll
            for (int ks = 0; ks < 4; ks++) {
                uint32_t b[4][2];
                #pragma unroll
                for (int p = 0; p < 2; p++) {
                    uint32_t addr = sbase + SM1_B + buf * B1_STAGE +
                        sw_off(nn_w + p * 16 + b_row_l, 2 * ks + b_ks_l);
                    LDSM_X4(b[2*p][0], b[2*p][1], b[2*p+1][0], b[2*p+1][1], addr);
                }
                uint32_t a[TT][4];
                #pragma unroll
                for (int t = 0; t < TT; t++) {
                    uint32_t addr = sbase + buf * A1_STAGE + t * 4096 +
                        sw_off(sm_w + a_row_l, 2 * ks + a_ks_l);
                    LDSM_X4(a[t][0], a[t][1], a[t][2], a[t][3], addr);
                }
                #pragma unroll
                for (int t = 0; t < TT; t++)
                    #pragma unroll
                    for (int n = 0; n < 4; n++)
                        IMMA16832(acci[t][n], a[t], b[n]);
            }
        }
        #pragma unroll
        for (int t = 0; t < TT; t++)
            #pragma unroll
            for (int n = 0; n < 4; n++)
                #pragma unroll
                for (int e = 0; e < 4; e++)
                    accf[t][n][e] = CFOLD * (float)acci[t][n][e];
    }

    // ---- fp16 phase: chunks 8-15, same ring ----
    for (int cc = 8; cc < 16; cc++) {
        const int buf = cc & (STG - 1);
        if (cc + 2 < 16) load_chunk(cc + 2, (cc + 2) & (STG - 1));
        if (cc <= 13)      asm volatile("cp.async.wait_group 2;" ::: "memory");
        else if (cc == 14) asm volatile("cp.async.wait_group 1;" ::: "memory");
        else               asm volatile("cp.async.wait_group 0;" ::: "memory");
        __syncthreads();

        #pragma unroll
        for (int ks = 0; ks < 4; ks++) {
            uint32_t b[4][2];
            #pragma unroll
            for (int p = 0; p < 2; p++) {
                uint32_t addr = sbase + SM1_B + buf * B1_STAGE +
                    sw_off(nn_w + p * 16 + b_row_l, 2 * ks + b_ks_l);
                LDSM_X4(b[2*p][0], b[2*p][1], b[2*p+1][0], b[2*p+1][1], addr);
            }
            uint32_t a[TT][4];
            #pragma unroll
            for (int t = 0; t < TT; t++) {
                uint32_t addr = sbase + buf * A1_STAGE + t * 4096 +
                    sw_off(sm_w + a_row_l, 2 * ks + a_ks_l);
                LDSM_X4(a[t][0], a[t][1], a[t][2], a[t][3], addr);
            }
            #pragma unroll
            for (int t = 0; t < TT; t++)
                #pragma unroll
                for (int n = 0; n < 4; n++)
                    MMAF16(accf[t][n], a[t], b[n]);
        }
    }

    // ---- epilogue: scan, store spikes, flag tight margins ----
    const float alpha = alphap[0];
    const int row_in_m = lane >> 2;
    const int col_pair = (lane & 3) * 2;

    #pragma unroll
    for (int n = 0; n < 4; n++)
        #pragma unroll
        for (int rh = 0; rh < 2; rh++) {
            const int site = bm0 + sm_w + row_in_m + rh * 8;
            const int col  = bn0 + nn_w + n * 8 + col_pair;
            float v0 = 0.f, v1 = 0.f, m0 = 1e9f, m1 = 1e9f;
            #pragma unroll
            for (int t = 0; t < TT; t++) {
                v0 += alpha * (accf[t][n][rh * 2]     - v0);
                v1 += alpha * (accf[t][n][rh * 2 + 1] - v1);
                m0 = fminf(m0, fabsf(v0 - 1.0f));
                m1 = fminf(m1, fabsf(v1 - 1.0f));
                bool s0 = (v0 >= 1.0f), s1 = (v1 >= 1.0f);
                v0 = s0 ? 0.f : v0;
                v1 = s1 ? 0.f : v1;
                char2 pk;
                pk.x = s0 ? 1 : 0;
                pk.y = s1 ? 1 : 0;
                *(char2*)(outp + ((size_t)t * BROWS + site) * HH + col) = pk;
            }
            if (m0 < EPS1) {
                int idx = atomicAdd(&g_cnt1, 1);
                if (idx < LCAP) g_list1[idx] = site * 2048 + col;
            }
            if (m1 < EPS1) {
                int idx = atomicAdd(&g_cnt1, 1);
                if (idx < LCAP) g_list1[idx] = site * 2048 + col + 1;
            }
        }
}

// ---------------- repair1: warp-per-neuron exact fp32 recompute ----------------
__global__ void repair_l1(const float* __restrict__ xraw,
                          const float* __restrict__ w1raw,
                          const float* __restrict__ alphap,
                          int8_t* __restrict__ s1)
{
    const int total = min(g_cnt1, LCAP);
    const float alpha = alphap[0];
    const int lane = threadIdx.x & 31;
    const int nwarp = (gridDim.x * blockDim.x) >> 5;
    for (int w = (blockIdx.x * blockDim.x + threadIdx.x) >> 5; w < total; w += nwarp) {
        const int e = g_list1[w];
        const int site = e >> 11, neuron = e & 2047;
        const float4* wp = (const float4*)(w1raw + (size_t)neuron * 512);
        float v = 0.f;
        for (int t = 0; t < TT; t++) {
            const float4* xp = (const float4*)(xraw + ((size_t)t * BROWS + site) * 512);
            float p = 0.f;
            #pragma unroll
            for (int k = 0; k < 4; k++) {
                float4 xv = xp[lane + k * 32], wv = wp[lane + k * 32];
                p += xv.x * wv.x + xv.y * wv.y + xv.z * wv.z + xv.w * wv.w;
            }
            #pragma unroll
            for (int o = 16; o; o >>= 1) p += __shfl_xor_sync(0xFFFFFFFF, p, o);
            v += alpha * (p - v);
            bool s = (v >= 1.0f);
            if (lane == 0)
                s1[((size_t)t * BROWS + site) * HH + neuron] = s ? 1 : 0;
            v = s ? 0.f : v;
        }
    }
}

// ---------------- layer2: int8 IMMA 2-digit + PLIF + flag ----------------
__global__ __launch_bounds__(256, 1)
void gemm_plif_l2(const int8_t* __restrict__ A,
                  const int8_t* __restrict__ Bw,
                  const float* __restrict__ alphap,
                  float* __restrict__ outp)
{
    extern __shared__ __align__(128) unsigned char smem_raw[];
    const uint32_t sbase = smem_u32(smem_raw);

    const int tid  = threadIdx.x;
    const int lane = tid & 31;
    const int wid  = tid >> 5;
    const int wm   = wid & 1;
    const int wn   = wid >> 1;
    const int sm_w = wm * 16;
    const int nn_w = wn * 32;

    const int bm0 = blockIdx.x * MS2;
    const int bn0 = blockIdx.y * TN2;
    const int NC  = KB2 / BK2;          // 32; digit fold at cc==15

    auto load_chunk = [&](int cc, int buf) {
        const int acol = (cc * BK2) % KA2;
        const int bcol = cc * BK2;
        #pragma unroll
        for (int i = tid; i < 1024; i += 256) {
            int kseg = i & 7, site = (i >> 3) & 31, t = i >> 8;
            const int8_t* g =
                A + ((size_t)t * BROWS + bm0 + site) * KA2 + acol + kseg * 16;
            CP_ASYNC16(sbase + buf * A2_STAGE + t * 4096 + sw_off(site, kseg), g);
        }
        #pragma unroll
        for (int i = tid; i < 1024; i += 256) {
            int kseg = i & 7, n = i >> 3;
            const int8_t* g =
                Bw + (size_t)(bn0 + n) * KB2 + bcol + kseg * 16;
            CP_ASYNC16(sbase + SM2_B + buf * B2_STAGE + sw_off(n, kseg), g);
        }
        CP_COMMIT();
    };

    int acc[TT][4][4];
    #pragma unroll
    for (int t = 0; t < TT; t++)
        #pragma unroll
        for (int n = 0; n < 4; n++)
            #pragma unroll
            for (int e = 0; e < 4; e++) acc[t][n][e] = 0;

    load_chunk(0, 0);
    load_chunk(1, 1);

    const int a_row_l = lane & 15;
    const int a_ks_l  = lane >> 4;
    const int b_row_l = (lane & 7) + ((lane & 16) >> 1);
    const int b_ks_l  = (lane >> 3) & 1;

    for (int cc = 0; cc < NC; cc++) {
        const int buf = cc & (STG - 1);
        if (cc + 2 < NC) load_chunk(cc + 2, (cc + 2) & (STG - 1));
        if (cc <= NC - 3)      asm volatile("cp.async.wait_group 2;" ::: "memory");
        else if (cc == NC - 2) asm volatile("cp.async.wait_group 1;" ::: "memory");
        else                   asm volatile("cp.async.wait_group 0;" ::: "memory");
        __syncthreads();

        #pragma unroll
        for (int ks = 0; ks < 4; ks++) {
            uint32_t b[4][2];
            #pragma unroll
            for (int p = 0; p < 2; p++) {
                uint32_t addr = sbase + SM2_B + buf * B2_STAGE +
                    sw_off(nn_w + p * 16 + b_row_l, 2 * ks + b_ks_l);
                LDSM_X4(b[2*p][0], b[2*p][1], b[2*p+1][0], b[2*p+1][1], addr);
            }
            uint32_t a[TT][4];
            #pragma unroll
            for (int t = 0; t < TT; t++) {
                uint32_t addr = sbase + buf * A2_STAGE + t * 4096 +
                    sw_off(sm_w + a_row_l, 2 * ks + a_ks_l);
                LDSM_X4(a[t][0], a[t][1], a[t][2], a[t][3], addr);
            }
            #pragma unroll
            for (int t = 0; t < TT; t++)
                #pragma unroll
                for (int n = 0; n < 4; n++)
                    IMMA16832(acc[t][n], a[t], b[n]);
        }

        if (cc == 15) {                 // exact digit fold (d1 plane done)
            #pragma unroll
            for (int t = 0; t < TT; t++)
                #pragma unroll
                for (int n = 0; n < 4; n++)
                    #pragma unroll
                    for (int e = 0; e < 4; e++) acc[t][n][e] <<= 7;
        }
    }

    // PLIF scan on y = acc * 2^-15, store spikes, flag tight margins
    const float alpha = alphap[0];
    const int row_in_m = lane >> 2;
    const int col_pair = (lane & 3) * 2;
    #pragma unroll
    for (int n = 0; n < 4; n++)
        #pragma unroll
        for (int rh = 0; rh < 2; rh++) {
            const int site = bm0 + sm_w + row_in_m + rh * 8;
            const int col  = bn0 + nn_w + n * 8 + col_pair;
            float v0 = 0.f, v1 = 0.f, m0 = 1e9f, m1 = 1e9f;
            #pragma unroll
            for (int t = 0; t < TT; t++) {
                float y0 = (float)acc[t][n][rh * 2]     * W2SCALE;
                float y1 = (float)acc[t][n][rh * 2 + 1] * W2SCALE;
                v0 += alpha * (y0 - v0);
                v1 += alpha * (y1 - v1);
                m0 = fminf(m0, fabsf(v0 - 1.0f));
                m1 = fminf(m1, fabsf(v1 - 1.0f));
                bool s0 = (v0 >= 1.0f), s1v = (v1 >= 1.0f);
                v0 = s0 ? 0.f : v0;
                v1 = s1v ? 0.f : v1;
                *(float2*)(outp + ((size_t)t * BROWS + site) * DD + col) =
                    make_float2(s0 ? 1.0f : 0.0f, s1v ? 1.0f : 0.0f);
            }
            if (m0 < EPS2) {
                int idx = atomicAdd(&g_cnt2, 1);
                if (idx < LCAP) g_list2[idx] = site * 512 + col;
            }
            if (m1 < EPS2) {
                int idx = atomicAdd(&g_cnt2, 1);
                if (idx < LCAP) g_list2[idx] = site * 512 + col + 1;
            }
        }
}

// ---------------- repair2: warp-per-neuron exact recompute of out ----------------
__global__ void repair_l2(const int8_t* __restrict__ s1,
                          const float* __restrict__ w2raw,
                          const float* __restrict__ alphap,
                          float* __restrict__ outp)
{
    const int total = min(g_cnt2, LCAP);
    const float alpha = alphap[0];
    const int lane = threadIdx.x & 31;
    const int nwarp = (gridDim.x * blockDim.x) >> 5;
    for (int w = (blockIdx.x * blockDim.x + threadIdx.x) >> 5; w < total; w += nwarp) {
        const int e = g_list2[w];
        const int site = e >> 9, col = e & 511;
        const float4* wp = (const float4*)(w2raw + (size_t)col * 2048);
        float v = 0.f;
        for (int t = 0; t < TT; t++) {
            const char4* sp = (const char4*)(s1 + ((size_t)t * BROWS + site) * HH);
            float p = 0.f;
            #pragma unroll
            for (int k = 0; k < 16; k++) {
                char4 sv = sp[lane + k * 32];
                float4 wv = wp[lane + k * 32];
                if (sv.x) p += wv.x;
                if (sv.y) p += wv.y;
                if (sv.z) p += wv.z;
                if (sv.w) p += wv.w;
            }
            #pragma unroll
            for (int o = 16; o; o >>= 1) p += __shfl_xor_sync(0xFFFFFFFF, p, o);
            v += alpha * (p - v);
            bool s = (v >= 1.0f);
            if (lane == 0)
                outp[((size_t)t * BROWS + site) * DD + col] = s ? 1.0f : 0.0f;
            v = s ? 0.f : v;
        }
    }
}

// ---------------- launch ----------------
extern "C" void kernel_launch(void* const* d_in, const int* in_sizes, int n_in,
                              void* d_out, int out_size)
{
    const float* x  = (const float*)d_in[0];
    const float* W1 = (const float*)d_in[1];
    const float* W2 = (const float*)d_in[2];
    const float* a1 = (const float*)d_in[3];
    const float* a2 = (const float*)d_in[4];
    float* out = (float*)d_out;

    __half *xh, *w1h;
    int8_t *xq, *w1q, *w2p, *s1;
    cudaGetSymbolAddress((void**)&xh,  g_xh);
    cudaGetSymbolAddress((void**)&xq,  g_xq);
    cudaGetSymbolAddress((void**)&w1h, g_w1h);
    cudaGetSymbolAddress((void**)&w1q, g_w1q);
    cudaGetSymbolAddress((void**)&w2p, g_w2);
    cudaGetSymbolAddress((void**)&s1,  g_s1);

    cudaFuncSetAttribute(gemm_plif_l1, cudaFuncAttributeMaxDynamicSharedMemorySize, SMEM1);
    cudaFuncSetAttribute(gemm_plif_l2, cudaFuncAttributeMaxDynamicSharedMemorySize, SMEM2);

    prep_x<<<(TT * BROWS * DD / 4) / 256, 256>>>((const float4*)x, xh, xq);
    prep_w1<<<(HH * DD) / 256, 256>>>(W1, w1h, w1q);
    pack_w2<<<(DD * HH) / 256, 256>>>(W2, w2p);

    // layer 1: int8 cross (K=1024) + fp16 hi*hi (K=512) -> s1 + flags
    dim3 g1(BROWS / MS1, HH / TN1);   // 256 x 16
    gemm_plif_l1<<<g1, 256, SMEM1>>>(xq, w1q, xh, w1h, a1, s1);
    repair_l1<<<512, 256>>>(x, W1, a1, s1);

    // layer 2: int8 IMMA 2-digit (K=4096) -> out + flags
    dim3 g2(BROWS / MS2, DD / TN2);   // 256 x 4
    gemm_plif_l2<<<g2, 256, SMEM2>>>(s1, w2p, a2, out);
    repair_l2<<<512, 256>>>(s1, W2, a2, out);
}

// round 13
// speedup vs baseline: 3.0289x; 1.1065x over previous
#include <cuda_runtime.h>
#include <cuda_bf16.h>
#include <cuda_fp16.h>
#include <cstdint>
#include <cstddef>

// ---------------- problem dims ----------------
constexpr int TT    = 4;
constexpr int BROWS = 8192;
constexpr int DD    = 512;
constexpr int HH    = 2048;
constexpr int KQ1   = 1024;           // layer1 int8 K: [q(lx) | q(x)]
constexpr int KH1   = 512;            // layer1 fp16 K (hi*hi)
constexpr int KA2   = 2048;           // layer2 A cols (s1 int8, wraps)
constexpr int KB2   = 4096;           // layer2 K: 2 digit planes x 2048 int8

// layer1 scales (fold constraint: 1/(IXL*IWH) == 1/(IXH*IWL), exact)
constexpr float IXH = 127.0f / 8.0f;
constexpr float IXL = 40000.0f;
constexpr float IWH = 127.0f / 0.32f;
constexpr float IWL = 1000000.0f;
constexpr float CFOLD = 8.0f / (127.0f * 1000000.0f);
constexpr float EPS1 = 2.5e-4f;
constexpr float W2SCALE = 1.0f / 32768.0f;
constexpr float EPS2 = 4e-3f;

// ---- layer1 tile: CTA 32 x 128 x 4t, 8 warps of 16x32, STG=3, 2 CTAs/SM ----
constexpr int MS1 = 32, TN1 = 128, STG = 3;
constexpr uint32_t A1_STAGE = 16384;
constexpr uint32_t B1_STAGE = 16384;
constexpr uint32_t SM1_B = STG * A1_STAGE;
constexpr uint32_t SMEM1 = STG * (A1_STAGE + B1_STAGE);   // 98304 (x2 = 192KB/SM)

// ---- layer2 tile ----
constexpr int MS2 = 32, TN2 = 128, BK2 = 128;
constexpr uint32_t A2_STAGE = 16384;
constexpr uint32_t B2_STAGE = 16384;
constexpr uint32_t SM2_B = STG * A2_STAGE;
constexpr uint32_t SMEM2 = STG * (A2_STAGE + B2_STAGE);   // 98304

// ---------------- scratch ----------------
__device__ __half  g_xh[(size_t)TT * BROWS * KH1];
__device__ int8_t  g_xq[(size_t)TT * BROWS * KQ1];
__device__ __half  g_w1h[(size_t)HH * KH1];
__device__ int8_t  g_w1q[(size_t)HH * KQ1];
__device__ int8_t  g_w2[(size_t)DD * KB2];
__device__ int8_t  g_s1[(size_t)TT * BROWS * HH];
constexpr int LCAP = 1 << 22;
__device__ int g_cnt1, g_cnt2;
__device__ int g_list1[LCAP];
__device__ int g_list2[LCAP];

// ---------------- PTX helpers ----------------
__device__ __forceinline__ uint32_t smem_u32(const void* p) {
    uint32_t a;
    asm("{ .reg .u64 t; cvta.to.shared.u64 t, %1; cvt.u32.u64 %0, t; }" : "=r"(a) : "l"(p));
    return a;
}
#define CP_ASYNC16(dst, src) \
    asm volatile("cp.async.cg.shared.global [%0], [%1], 16;" :: "r"(dst), "l"(src) : "memory")
#define CP_COMMIT() asm volatile("cp.async.commit_group;" ::: "memory")

#define LDSM_X4(r0, r1, r2, r3, addr)                                        \
    asm volatile("ldmatrix.sync.aligned.m8n8.x4.shared.b16 {%0,%1,%2,%3}, [%4];" \
        : "=r"(r0), "=r"(r1), "=r"(r2), "=r"(r3) : "r"(addr))

#define MMAF16(d, a, b)                                                      \
    asm volatile("mma.sync.aligned.m16n8k16.row.col.f32.f16.f16.f32 "        \
        "{%0,%1,%2,%3}, {%4,%5,%6,%7}, {%8,%9}, {%0,%1,%2,%3};"              \
        : "+f"((d)[0]), "+f"((d)[1]), "+f"((d)[2]), "+f"((d)[3])             \
        : "r"((a)[0]), "r"((a)[1]), "r"((a)[2]), "r"((a)[3]),                \
          "r"((b)[0]), "r"((b)[1]))

#define IMMA16832(d, a, b)                                                   \
    asm volatile("mma.sync.aligned.m16n8k32.row.col.s32.s8.s8.s32 "          \
        "{%0,%1,%2,%3}, {%4,%5,%6,%7}, {%8,%9}, {%0,%1,%2,%3};"              \
        : "+r"((d)[0]), "+r"((d)[1]), "+r"((d)[2]), "+r"((d)[3])             \
        : "r"((a)[0]), "r"((a)[1]), "r"((a)[2]), "r"((a)[3]),                \
          "r"((b)[0]), "r"((b)[1]))

__device__ __forceinline__ uint32_t sw_off(uint32_t row, uint32_t kseg) {
    return row * 128 + ((kseg ^ (row & 7)) << 4);
}
__device__ __forceinline__ int8_t q8(float v, float inv) {
    int q = __float2int_rn(v * inv);
    q = max(-127, min(127, q));
    return (int8_t)q;
}

// ---------------- prep kernels ----------------
__global__ void prep_x(const float4* __restrict__ x,
                       __half* __restrict__ xh,
                       int8_t* __restrict__ xq)
{
    if (blockIdx.x == 0 && threadIdx.x == 0) { g_cnt1 = 0; g_cnt2 = 0; }
    size_t i = (size_t)blockIdx.x * blockDim.x + threadIdx.x;
    float4 v = x[i];
    int r = (int)(i >> 7);
    int d = ((int)i & 127) * 4;
    __half h0 = __float2half_rn(v.x), h1 = __float2half_rn(v.y);
    __half h2 = __float2half_rn(v.z), h3 = __float2half_rn(v.w);
    __half2* hp = (__half2*)(xh + (size_t)r * KH1 + d);
    hp[0] = __halves2half2(h0, h1);
    hp[1] = __halves2half2(h2, h3);
    float l0 = v.x - __half2float(h0), l1 = v.y - __half2float(h1);
    float l2 = v.z - __half2float(h2), l3 = v.w - __half2float(h3);
    char4 ql = make_char4(q8(l0, IXL), q8(l1, IXL), q8(l2, IXL), q8(l3, IXL));
    char4 qx = make_char4(q8(v.x, IXH), q8(v.y, IXH), q8(v.z, IXH), q8(v.w, IXH));
    *(char4*)(xq + (size_t)r * KQ1 + d)       = ql;
    *(char4*)(xq + (size_t)r * KQ1 + 512 + d) = qx;
}
__global__ void prep_w1(const float* __restrict__ w,
                        __half* __restrict__ wh,
                        int8_t* __restrict__ wq)
{
    size_t i = (size_t)blockIdx.x * blockDim.x + threadIdx.x;
    int r = (int)(i >> 9);
    int d = (int)(i & 511);
    float v = w[i];
    __half hb = __float2half_rn(v);
    float hi = __half2float(hb);
    wh[(size_t)r * KH1 + d] = hb;
    wq[(size_t)r * KQ1 + d]       = q8(hi, IWH);
    wq[(size_t)r * KQ1 + 512 + d] = q8(v - hi, IWL);
}
__global__ void pack_w2(const float* __restrict__ w, int8_t* __restrict__ o)
{
    size_t i = (size_t)blockIdx.x * blockDim.x + threadIdx.x;
    int r = (int)(i >> 11);
    int c = (int)(i & 2047);
    int v = (int)lrintf(w[i] * 32768.0f);
    v = max(-8192, min(8192, v));
    int d0 = ((v & 127) ^ 64) - 64;
    int d1 = (v - d0) >> 7;
    size_t base = (size_t)r * KB2;
    o[base + c]        = (int8_t)d1;
    o[base + 2048 + c] = (int8_t)d0;
}

// ---------------- layer1: unified int8+fp16 pipeline, 2 CTAs/SM ----------------
__global__ __launch_bounds__(256, 2)
void gemm_plif_l1(const void* __restrict__ Aq, const void* __restrict__ Bq,
                  const void* __restrict__ Ah, const void* __restrict__ Bh,
                  const float* __restrict__ alphap,
                  int8_t* __restrict__ outp)
{
    extern __shared__ __align__(128) unsigned char smem_raw[];
    const uint32_t sbase = smem_u32(smem_raw);

    const int tid  = threadIdx.x;
    const int lane = tid & 31;
    const int wid  = tid >> 5;
    const int wm   = wid & 1;
    const int wn   = wid >> 1;
    const int sm_w = wm * 16;
    const int nn_w = wn * 32;

    const int bm0 = blockIdx.x * MS1;
    const int bn0 = blockIdx.y * TN1;

    const int a_row_l = lane & 15;
    const int a_ks_l  = lane >> 4;
    const int b_row_l = (lane & 7) + ((lane & 16) >> 1);
    const int b_ks_l  = (lane >> 3) & 1;

    // uniform loader; chunks 0-7 int8, 8-15 fp16 (both 1024B rows)
    auto load_chunk = [&](int cc, int buf) {
        const char* Ab = (const char*)((cc < 8) ? Aq : Ah);
        const char* Bb = (const char*)((cc < 8) ? Bq : Bh);
        const int bcol = (cc & 7) * 128;
        #pragma unroll
        for (int i = tid; i < 1024; i += 256) {
            int kseg = i & 7, site = (i >> 3) & 31, t = i >> 8;
            const char* g = Ab + ((size_t)t * BROWS + bm0 + site) * 1024
                               + bcol + kseg * 16;
            CP_ASYNC16(sbase + buf * A1_STAGE + t * 4096 + sw_off(site, kseg), g);
        }
        #pragma unroll
        for (int i = tid; i < 1024; i += 256) {
            int kseg = i & 7, n = i >> 3;
            const char* g = Bb + (size_t)(bn0 + n) * 1024 + bcol + kseg * 16;
            CP_ASYNC16(sbase + SM1_B + buf * B1_STAGE + sw_off(n, kseg), g);
        }
        CP_COMMIT();
    };

    float accf[TT][4][4];
    load_chunk(0, 0);
    load_chunk(1, 1);

    {   // ---- int8 phase: chunks 0-7 (ring continues into fp16 chunks) ----
        int acci[TT][4][4];
        #pragma unroll
        for (int t = 0; t < TT; t++)
            #pragma unroll
            for (int n = 0; n < 4; n++)
                #pragma unroll
                for (int e = 0; e < 4; e++) acci[t][n][e] = 0;

        for (int cc = 0; cc < 8; cc++) {
            const int buf = cc % STG;
            asm volatile("cp.async.wait_group 1;" ::: "memory");
            __syncthreads();
            load_chunk(cc + 2, (cc + 2) % STG);

            #pragma unroll
            for (int ks = 0; ks < 4; ks++) {
                uint32_t b[4][2];
                #pragma unroll
                for (int p = 0; p < 2; p++) {
                    uint32_t addr = sbase + SM1_B + buf * B1_STAGE +
                        sw_off(nn_w + p * 16 + b_row_l, 2 * ks + b_ks_l);
                    LDSM_X4(b[2*p][0], b[2*p][1], b[2*p+1][0], b[2*p+1][1], addr);
                }
                uint32_t a[TT][4];
                #pragma unroll
                for (int t = 0; t < TT; t++) {
                    uint32_t addr = sbase + buf * A1_STAGE + t * 4096 +
                        sw_off(sm_w + a_row_l, 2 * ks + a_ks_l);
                    LDSM_X4(a[t][0], a[t][1], a[t][2], a[t][3], addr);
                }
                #pragma unroll
                for (int t = 0; t < TT; t++)
                    #pragma unroll
                    for (int n = 0; n < 4; n++)
                        IMMA16832(acci[t][n], a[t], b[n]);
            }
        }
        // fold: acci dies here, accf born here (disjoint live ranges)
        #pragma unroll
        for (int t = 0; t < TT; t++)
            #pragma unroll
            for (int n = 0; n < 4; n++)
                #pragma unroll
                for (int e = 0; e < 4; e++)
                    accf[t][n][e] = CFOLD * (float)acci[t][n][e];
    }

    // ---- fp16 phase: chunks 8-15, same ring, no drain ----
    for (int cc = 8; cc < 16; cc++) {
        const int buf = cc % STG;
        if (cc < 15) asm volatile("cp.async.wait_group 1;" ::: "memory");
        else         asm volatile("cp.async.wait_group 0;" ::: "memory");
        __syncthreads();
        if (cc + 2 < 16) load_chunk(cc + 2, (cc + 2) % STG);

        #pragma unroll
        for (int ks = 0; ks < 4; ks++) {
            uint32_t b[4][2];
            #pragma unroll
            for (int p = 0; p < 2; p++) {
                uint32_t addr = sbase + SM1_B + buf * B1_STAGE +
                    sw_off(nn_w + p * 16 + b_row_l, 2 * ks + b_ks_l);
                LDSM_X4(b[2*p][0], b[2*p][1], b[2*p+1][0], b[2*p+1][1], addr);
            }
            uint32_t a[TT][4];
            #pragma unroll
            for (int t = 0; t < TT; t++) {
                uint32_t addr = sbase + buf * A1_STAGE + t * 4096 +
                    sw_off(sm_w + a_row_l, 2 * ks + a_ks_l);
                LDSM_X4(a[t][0], a[t][1], a[t][2], a[t][3], addr);
            }
            #pragma unroll
            for (int t = 0; t < TT; t++)
                #pragma unroll
                for (int n = 0; n < 4; n++)
                    MMAF16(accf[t][n], a[t], b[n]);
        }
    }

    // ---- epilogue: scan, store spikes, flag tight margins ----
    const float alpha = alphap[0];
    const int row_in_m = lane >> 2;
    const int col_pair = (lane & 3) * 2;

    #pragma unroll
    for (int n = 0; n < 4; n++)
        #pragma unroll
        for (int rh = 0; rh < 2; rh++) {
            const int site = bm0 + sm_w + row_in_m + rh * 8;
            const int col  = bn0 + nn_w + n * 8 + col_pair;
            float v0 = 0.f, v1 = 0.f, m0 = 1e9f, m1 = 1e9f;
            #pragma unroll
            for (int t = 0; t < TT; t++) {
                v0 += alpha * (accf[t][n][rh * 2]     - v0);
                v1 += alpha * (accf[t][n][rh * 2 + 1] - v1);
                m0 = fminf(m0, fabsf(v0 - 1.0f));
                m1 = fminf(m1, fabsf(v1 - 1.0f));
                bool s0 = (v0 >= 1.0f), s1 = (v1 >= 1.0f);
                v0 = s0 ? 0.f : v0;
                v1 = s1 ? 0.f : v1;
                char2 pk;
                pk.x = s0 ? 1 : 0;
                pk.y = s1 ? 1 : 0;
                *(char2*)(outp + ((size_t)t * BROWS + site) * HH + col) = pk;
            }
            if (m0 < EPS1) {
                int idx = atomicAdd(&g_cnt1, 1);
                if (idx < LCAP) g_list1[idx] = site * 2048 + col;
            }
            if (m1 < EPS1) {
                int idx = atomicAdd(&g_cnt1, 1);
                if (idx < LCAP) g_list1[idx] = site * 2048 + col + 1;
            }
        }
}

// ---------------- repair1: warp-per-neuron exact fp32 recompute ----------------
__global__ void repair_l1(const float* __restrict__ xraw,
                          const float* __restrict__ w1raw,
                          const float* __restrict__ alphap,
                          int8_t* __restrict__ s1)
{
    const int total = min(g_cnt1, LCAP);
    const float alpha = alphap[0];
    const int lane = threadIdx.x & 31;
    const int nwarp = (gridDim.x * blockDim.x) >> 5;
    for (int w = (blockIdx.x * blockDim.x + threadIdx.x) >> 5; w < total; w += nwarp) {
        const int e = g_list1[w];
        const int site = e >> 11, neuron = e & 2047;
        const float4* wp = (const float4*)(w1raw + (size_t)neuron * 512);
        float v = 0.f;
        for (int t = 0; t < TT; t++) {
            const float4* xp = (const float4*)(xraw + ((size_t)t * BROWS + site) * 512);
            float p = 0.f;
            #pragma unroll
            for (int k = 0; k < 4; k++) {
                float4 xv = xp[lane + k * 32], wv = wp[lane + k * 32];
                p += xv.x * wv.x + xv.y * wv.y + xv.z * wv.z + xv.w * wv.w;
            }
            #pragma unroll
            for (int o = 16; o; o >>= 1) p += __shfl_xor_sync(0xFFFFFFFF, p, o);
            v += alpha * (p - v);
            bool s = (v >= 1.0f);
            if (lane == 0)
                s1[((size_t)t * BROWS + site) * HH + neuron] = s ? 1 : 0;
            v = s ? 0.f : v;
        }
    }
}

// ---------------- layer2: int8 IMMA 2-digit + PLIF + flag, 2 CTAs/SM ----------------
__global__ __launch_bounds__(256, 2)
void gemm_plif_l2(const int8_t* __restrict__ A,
                  const int8_t* __restrict__ Bw,
                  const float* __restrict__ alphap,
                  float* __restrict__ outp)
{
    extern __shared__ __align__(128) unsigned char smem_raw[];
    const uint32_t sbase = smem_u32(smem_raw);

    const int tid  = threadIdx.x;
    const int lane = tid & 31;
    const int wid  = tid >> 5;
    const int wm   = wid & 1;
    const int wn   = wid >> 1;
    const int sm_w = wm * 16;
    const int nn_w = wn * 32;

    const int bm0 = blockIdx.x * MS2;
    const int bn0 = blockIdx.y * TN2;
    const int NC  = KB2 / BK2;          // 32; digit fold at cc==15

    auto load_chunk = [&](int cc, int buf) {
        const int acol = (cc * BK2) % KA2;
        const int bcol = cc * BK2;
        #pragma unroll
        for (int i = tid; i < 1024; i += 256) {
            int kseg = i & 7, site = (i >> 3) & 31, t = i >> 8;
            const int8_t* g =
                A + ((size_t)t * BROWS + bm0 + site) * KA2 + acol + kseg * 16;
            CP_ASYNC16(sbase + buf * A2_STAGE + t * 4096 + sw_off(site, kseg), g);
        }
        #pragma unroll
        for (int i = tid; i < 1024; i += 256) {
            int kseg = i & 7, n = i >> 3;
            const int8_t* g =
                Bw + (size_t)(bn0 + n) * KB2 + bcol + kseg * 16;
            CP_ASYNC16(sbase + SM2_B + buf * B2_STAGE + sw_off(n, kseg), g);
        }
        CP_COMMIT();
    };

    int acc[TT][4][4];
    #pragma unroll
    for (int t = 0; t < TT; t++)
        #pragma unroll
        for (int n = 0; n < 4; n++)
            #pragma unroll
            for (int e = 0; e < 4; e++) acc[t][n][e] = 0;

    load_chunk(0, 0);
    load_chunk(1, 1);

    const int a_row_l = lane & 15;
    const int a_ks_l  = lane >> 4;
    const int b_row_l = (lane & 7) + ((lane & 16) >> 1);
    const int b_ks_l  = (lane >> 3) & 1;

    for (int cc = 0; cc < NC; cc++) {
        const int buf = cc % STG;
        if (cc < NC - 1) asm volatile("cp.async.wait_group 1;" ::: "memory");
        else             asm volatile("cp.async.wait_group 0;" ::: "memory");
        __syncthreads();
        if (cc + 2 < NC) load_chunk(cc + 2, (cc + 2) % STG);

        #pragma unroll
        for (int ks = 0; ks < 4; ks++) {
            uint32_t b[4][2];
            #pragma unroll
            for (int p = 0; p < 2; p++) {
                uint32_t addr = sbase + SM2_B + buf * B2_STAGE +
                    sw_off(nn_w + p * 16 + b_row_l, 2 * ks + b_ks_l);
                LDSM_X4(b[2*p][0], b[2*p][1], b[2*p+1][0], b[2*p+1][1], addr);
            }
            uint32_t a[TT][4];
            #pragma unroll
            for (int t = 0; t < TT; t++) {
                uint32_t addr = sbase + buf * A2_STAGE + t * 4096 +
                    sw_off(sm_w + a_row_l, 2 * ks + a_ks_l);
                LDSM_X4(a[t][0], a[t][1], a[t][2], a[t][3], addr);
            }
            #pragma unroll
            for (int t = 0; t < TT; t++)
                #pragma unroll
                for (int n = 0; n < 4; n++)
                    IMMA16832(acc[t][n], a[t], b[n]);
        }

        if (cc == 15) {                 // exact digit fold
            #pragma unroll
            for (int t = 0; t < TT; t++)
                #pragma unroll
                for (int n = 0; n < 4; n++)
                    #pragma unroll
                    for (int e = 0; e < 4; e++) acc[t][n][e] <<= 7;
        }
    }

    // PLIF scan on y = acc * 2^-15, store spikes, flag tight margins
    const float alpha = alphap[0];
    const int row_in_m = lane >> 2;
    const int col_pair = (lane & 3) * 2;
    #pragma unroll
    for (int n = 0; n < 4; n++)
        #pragma unroll
        for (int rh = 0; rh < 2; rh++) {
            const int site = bm0 + sm_w + row_in_m + rh * 8;
            const int col  = bn0 + nn_w + n * 8 + col_pair;
            float v0 = 0.f, v1 = 0.f, m0 = 1e9f, m1 = 1e9f;
            #pragma unroll
            for (int t = 0; t < TT; t++) {
                float y0 = (float)acc[t][n][rh * 2]     * W2SCALE;
                float y1 = (float)acc[t][n][rh * 2 + 1] * W2SCALE;
                v0 += alpha * (y0 - v0);
                v1 += alpha * (y1 - v1);
                m0 = fminf(m0, fabsf(v0 - 1.0f));
                m1 = fminf(m1, fabsf(v1 - 1.0f));
                bool s0 = (v0 >= 1.0f), s1v = (v1 >= 1.0f);
                v0 = s0 ? 0.f : v0;
                v1 = s1v ? 0.f : v1;
                *(float2*)(outp + ((size_t)t * BROWS + site) * DD + col) =
                    make_float2(s0 ? 1.0f : 0.0f, s1v ? 1.0f : 0.0f);
            }
            if (m0 < EPS2) {
                int idx = atomicAdd(&g_cnt2, 1);
                if (idx < LCAP) g_list2[idx] = site * 512 + col;
            }
            if (m1 < EPS2) {
                int idx = atomicAdd(&g_cnt2, 1);
                if (idx < LCAP) g_list2[idx] = site * 512 + col + 1;
            }
        }
}

// ---------------- repair2: warp-per-neuron exact recompute of out ----------------
__global__ void repair_l2(const int8_t* __restrict__ s1,
                          const float* __restrict__ w2raw,
                          const float* __restrict__ alphap,
                          float* __restrict__ outp)
{
    const int total = min(g_cnt2, LCAP);
    const float alpha = alphap[0];
    const int lane = threadIdx.x & 31;
    const int nwarp = (gridDim.x * blockDim.x) >> 5;
    for (int w = (blockIdx.x * blockDim.x + threadIdx.x) >> 5; w < total; w += nwarp) {
        const int e = g_list2[w];
        const int site = e >> 9, col = e & 511;
        const float4* wp = (const float4*)(w2raw + (size_t)col * 2048);
        float v = 0.f;
        for (int t = 0; t < TT; t++) {
            const char4* sp = (const char4*)(s1 + ((size_t)t * BROWS + site) * HH);
            float p = 0.f;
            #pragma unroll
            for (int k = 0; k < 16; k++) {
                char4 sv = sp[lane + k * 32];
                float4 wv = wp[lane + k * 32];
                if (sv.x) p += wv.x;
                if (sv.y) p += wv.y;
                if (sv.z) p += wv.z;
                if (sv.w) p += wv.w;
            }
            #pragma unroll
            for (int o = 16; o; o >>= 1) p += __shfl_xor_sync(0xFFFFFFFF, p, o);
            v += alpha * (p - v);
            bool s = (v >= 1.0f);
            if (lane == 0)
                outp[((size_t)t * BROWS + site) * DD + col] = s ? 1.0f : 0.0f;
            v = s ? 0.f : v;
        }
    }
}

// ---------------- launch ----------------
extern "C" void kernel_launch(void* const* d_in, const int* in_sizes, int n_in,
                              void* d_out, int out_size)
{
    const float* x  = (const float*)d_in[0];
    const float* W1 = (const float*)d_in[1];
    const float* W2 = (const float*)d_in[2];
    const float* a1 = (const float*)d_in[3];
    const float* a2 = (const float*)d_in[4];
    float* out = (float*)d_out;

    __half *xh, *w1h;
    int8_t *xq, *w1q, *w2p, *s1;
    cudaGetSymbolAddress((void**)&xh,  g_xh);
    cudaGetSymbolAddress((void**)&xq,  g_xq);
    cudaGetSymbolAddress((void**)&w1h, g_w1h);
    cudaGetSymbolAddress((void**)&w1q, g_w1q);
    cudaGetSymbolAddress((void**)&w2p, g_w2);
    cudaGetSymbolAddress((void**)&s1,  g_s1);

    cudaFuncSetAttribute(gemm_plif_l1, cudaFuncAttributeMaxDynamicSharedMemorySize, SMEM1);
    cudaFuncSetAttribute(gemm_plif_l2, cudaFuncAttributeMaxDynamicSharedMemorySize, SMEM2);

    prep_x<<<(TT * BROWS * DD / 4) / 256, 256>>>((const float4*)x, xh, xq);
    prep_w1<<<(HH * DD) / 256, 256>>>(W1, w1h, w1q);
    pack_w2<<<(DD * HH) / 256, 256>>>(W2, w2p);

    // layer 1: int8 cross (K=1024) + fp16 hi*hi (K=512) -> s1 + flags
    dim3 g1(BROWS / MS1, HH / TN1);   // 256 x 16
    gemm_plif_l1<<<g1, 256, SMEM1>>>(xq, w1q, xh, w1h, a1, s1);
    repair_l1<<<512, 256>>>(x, W1, a1, s1);

    // layer 2: int8 IMMA 2-digit (K=4096) -> out + flags
    dim3 g2(BROWS / MS2, DD / TN2);   // 256 x 4
    gemm_plif_l2<<<g2, 256, SMEM2>>>(s1, w2p, a2, out);
    repair_l2<<<512, 256>>>(s1, W2, a2, out);
}

// round 14
// speedup vs baseline: 3.2560x; 1.0750x over previous
#include <cuda_runtime.h>
#include <cuda_bf16.h>
#include <cuda_fp16.h>
#include <cstdint>
#include <cstddef>

// ---------------- problem dims ----------------
constexpr int TT    = 4;
constexpr int BROWS = 8192;
constexpr int DD    = 512;
constexpr int HH    = 2048;
constexpr int KQ1   = 1024;           // layer1 int8 K: [q(lx) | q(x)]
constexpr int KH1   = 512;            // layer1 fp16 K (hi*hi)
constexpr int KA2   = 2048;           // layer2 A cols (s1 int8, wraps)
constexpr int KB2   = 4096;           // layer2 K: 2 digit planes x 2048 int8

// layer1 scales (fold constraint: 1/(IXL*IWH) == 1/(IXH*IWL), exact)
constexpr float IXH = 127.0f / 8.0f;
constexpr float IXL = 40000.0f;
constexpr float IWH = 127.0f / 0.32f;
constexpr float IWL = 1000000.0f;
constexpr float CFOLD = 8.0f / (127.0f * 1000000.0f);
constexpr float EPS1 = 2.5e-4f;
constexpr float W2SCALE = 1.0f / 32768.0f;
constexpr float EPS2 = 4e-3f;

// ---- layer1 tile: CTA 32 x 128 x 4t, 8 warps of 16x32, STG=3, 2 CTAs/SM ----
constexpr int MS1 = 32, TN1 = 128, STG = 3;
constexpr uint32_t A1_STAGE = 16384;
constexpr uint32_t B1_STAGE = 16384;
constexpr uint32_t SM1_B = STG * A1_STAGE;
constexpr uint32_t SMEM1 = STG * (A1_STAGE + B1_STAGE);   // 98304

// ---- layer2 tile ----
constexpr int MS2 = 32, TN2 = 128, BK2 = 128;
constexpr uint32_t A2_STAGE = 16384;
constexpr uint32_t B2_STAGE = 16384;
constexpr uint32_t SM2_B = STG * A2_STAGE;
constexpr uint32_t SMEM2 = STG * (A2_STAGE + B2_STAGE);   // 98304

// ---------------- scratch ----------------
__device__ __half  g_xh[(size_t)TT * BROWS * KH1];
__device__ int8_t  g_xq[(size_t)TT * BROWS * KQ1];
__device__ __half  g_w1h[(size_t)HH * KH1];
__device__ int8_t  g_w1q[(size_t)HH * KQ1];
__device__ int8_t  g_w2[(size_t)DD * KB2];
__device__ int8_t  g_s1[(size_t)TT * BROWS * HH];
constexpr int LCAP = 1 << 22;
__device__ int g_cnt1, g_cnt2;
__device__ int g_list1[LCAP];
__device__ int g_list2[LCAP];

// ---------------- PTX helpers ----------------
__device__ __forceinline__ uint32_t smem_u32(const void* p) {
    uint32_t a;
    asm("{ .reg .u64 t; cvta.to.shared.u64 t, %1; cvt.u32.u64 %0, t; }" : "=r"(a) : "l"(p));
    return a;
}
#define CP_ASYNC16(dst, src) \
    asm volatile("cp.async.cg.shared.global [%0], [%1], 16;" :: "r"(dst), "l"(src) : "memory")
#define CP_COMMIT() asm volatile("cp.async.commit_group;" ::: "memory")

#define LDSM_X4(r0, r1, r2, r3, addr)                                        \
    asm volatile("ldmatrix.sync.aligned.m8n8.x4.shared.b16 {%0,%1,%2,%3}, [%4];" \
        : "=r"(r0), "=r"(r1), "=r"(r2), "=r"(r3) : "r"(addr))

#define MMAF16(d, a, b)                                                      \
    asm volatile("mma.sync.aligned.m16n8k16.row.col.f32.f16.f16.f32 "        \
        "{%0,%1,%2,%3}, {%4,%5,%6,%7}, {%8,%9}, {%0,%1,%2,%3};"              \
        : "+f"((d)[0]), "+f"((d)[1]), "+f"((d)[2]), "+f"((d)[3])             \
        : "r"((a)[0]), "r"((a)[1]), "r"((a)[2]), "r"((a)[3]),                \
          "r"((b)[0]), "r"((b)[1]))

#define IMMA16832(d, a, b)                                                   \
    asm volatile("mma.sync.aligned.m16n8k32.row.col.s32.s8.s8.s32 "          \
        "{%0,%1,%2,%3}, {%4,%5,%6,%7}, {%8,%9}, {%0,%1,%2,%3};"              \
        : "+r"((d)[0]), "+r"((d)[1]), "+r"((d)[2]), "+r"((d)[3])             \
        : "r"((a)[0]), "r"((a)[1]), "r"((a)[2]), "r"((a)[3]),                \
          "r"((b)[0]), "r"((b)[1]))

__device__ __forceinline__ uint32_t sw_off(uint32_t row, uint32_t kseg) {
    return row * 128 + ((kseg ^ (row & 7)) << 4);
}
__device__ __forceinline__ int8_t q8(float v, float inv) {
    int q = __float2int_rn(v * inv);
    q = max(-127, min(127, q));
    return (int8_t)q;
}
// warp-aggregated flag push (flags are rare; early-out on no-flag)
__device__ __forceinline__ void push_flag(bool flag, int val, int* cnt, int* list) {
    unsigned bal = __ballot_sync(0xFFFFFFFF, flag);
    if (!bal) return;
    int leader = __ffs(bal) - 1;
    int lane = threadIdx.x & 31;
    int base = 0;
    if (lane == leader) base = atomicAdd(cnt, __popc(bal));
    base = __shfl_sync(0xFFFFFFFF, base, leader);
    if (flag) {
        int idx = base + __popc(bal & ((1u << lane) - 1));
        if (idx < LCAP) list[idx] = val;
    }
}

// ---------------- prep kernels ----------------
__global__ void prep_x(const float4* __restrict__ x,
                       __half* __restrict__ xh,
                       int8_t* __restrict__ xq)
{
    if (blockIdx.x == 0 && threadIdx.x == 0) { g_cnt1 = 0; g_cnt2 = 0; }
    size_t i = (size_t)blockIdx.x * blockDim.x + threadIdx.x;
    float4 v = x[i];
    int r = (int)(i >> 7);
    int d = ((int)i & 127) * 4;
    __half h0 = __float2half_rn(v.x), h1 = __float2half_rn(v.y);
    __half h2 = __float2half_rn(v.z), h3 = __float2half_rn(v.w);
    __half2* hp = (__half2*)(xh + (size_t)r * KH1 + d);
    hp[0] = __halves2half2(h0, h1);
    hp[1] = __halves2half2(h2, h3);
    float l0 = v.x - __half2float(h0), l1 = v.y - __half2float(h1);
    float l2 = v.z - __half2float(h2), l3 = v.w - __half2float(h3);
    char4 ql = make_char4(q8(l0, IXL), q8(l1, IXL), q8(l2, IXL), q8(l3, IXL));
    char4 qx = make_char4(q8(v.x, IXH), q8(v.y, IXH), q8(v.z, IXH), q8(v.w, IXH));
    *(char4*)(xq + (size_t)r * KQ1 + d)       = ql;
    *(char4*)(xq + (size_t)r * KQ1 + 512 + d) = qx;
}
__global__ void prep_w1(const float* __restrict__ w,
                        __half* __restrict__ wh,
                        int8_t* __restrict__ wq)
{
    size_t i = (size_t)blockIdx.x * blockDim.x + threadIdx.x;
    int r = (int)(i >> 9);
    int d = (int)(i & 511);
    float v = w[i];
    __half hb = __float2half_rn(v);
    float hi = __half2float(hb);
    wh[(size_t)r * KH1 + d] = hb;
    wq[(size_t)r * KQ1 + d]       = q8(hi, IWH);
    wq[(size_t)r * KQ1 + 512 + d] = q8(v - hi, IWL);
}
__global__ void pack_w2(const float* __restrict__ w, int8_t* __restrict__ o)
{
    size_t i = (size_t)blockIdx.x * blockDim.x + threadIdx.x;
    int r = (int)(i >> 11);
    int c = (int)(i & 2047);
    int v = (int)lrintf(w[i] * 32768.0f);
    v = max(-8192, min(8192, v));
    int d0 = ((v & 127) ^ 64) - 64;
    int d1 = (v - d0) >> 7;
    size_t base = (size_t)r * KB2;
    o[base + c]        = (int8_t)d1;
    o[base + 2048 + c] = (int8_t)d0;
}

// ---------------- layer1: unified int8+fp16 pipeline, 2 CTAs/SM ----------------
__global__ __launch_bounds__(256, 2)
void gemm_plif_l1(const void* __restrict__ Aq, const void* __restrict__ Bq,
                  const void* __restrict__ Ah, const void* __restrict__ Bh,
                  const float* __restrict__ alphap,
                  int8_t* __restrict__ outp)
{
    extern __shared__ __align__(128) unsigned char smem_raw[];
    const uint32_t sbase = smem_u32(smem_raw);

    const int tid  = threadIdx.x;
    const int lane = tid & 31;
    const int wid  = tid >> 5;
    const int wm   = wid & 1;
    const int wn   = wid >> 1;
    const int sm_w = wm * 16;
    const int nn_w = wn * 32;

    const int bm0 = blockIdx.x * MS1;
    const int bn0 = blockIdx.y * TN1;

    const int a_row_l = lane & 15;
    const int a_ks_l  = lane >> 4;
    const int b_row_l = (lane & 7) + ((lane & 16) >> 1);
    const int b_ks_l  = (lane >> 3) & 1;

    // ---- precomputed loader offsets (chunk-invariant) ----
    uint32_t ag[4], as[4], bg[4], bs[4];
    #pragma unroll
    for (int j = 0; j < 4; j++) {
        int i = tid + j * 256;
        int kseg = i & 7, site = (i >> 3) & 31, t = i >> 8;
        ag[j] = (uint32_t)((t * BROWS + bm0 + site) * 1024 + kseg * 16);
        as[j] = (uint32_t)(t * 4096 + sw_off(site, kseg));
        int n = i >> 3;
        bg[j] = (uint32_t)((bn0 + n) * 1024 + kseg * 16);
        bs[j] = sw_off(n, kseg);
    }

    auto load_chunk = [&](int cc, int buf) {
        const char* Ab = (const char*)((cc < 8) ? Aq : Ah);
        const char* Bb = (const char*)((cc < 8) ? Bq : Bh);
        const uint32_t bcol = (cc & 7) * 128;
        const uint32_t abase = sbase + buf * A1_STAGE;
        const uint32_t bbase = sbase + SM1_B + buf * B1_STAGE;
        #pragma unroll
        for (int j = 0; j < 4; j++)
            CP_ASYNC16(abase + as[j], Ab + ag[j] + bcol);
        #pragma unroll
        for (int j = 0; j < 4; j++)
            CP_ASYNC16(bbase + bs[j], Bb + bg[j] + bcol);
        CP_COMMIT();
    };

    float accf[TT][4][4];
    load_chunk(0, 0);
    load_chunk(1, 1);

    {   // ---- int8 phase: chunks 0-7 (ring continues into fp16 chunks) ----
        int acci[TT][4][4];
        #pragma unroll
        for (int t = 0; t < TT; t++)
            #pragma unroll
            for (int n = 0; n < 4; n++)
                #pragma unroll
                for (int e = 0; e < 4; e++) acci[t][n][e] = 0;

        int buf = 0, pbuf = 2;
        for (int cc = 0; cc < 8; cc++) {
            asm volatile("cp.async.wait_group 1;" ::: "memory");
            __syncthreads();
            load_chunk(cc + 2, pbuf);

            #pragma unroll
            for (int ks = 0; ks < 4; ks++) {
                uint32_t b[4][2];
                #pragma unroll
                for (int p = 0; p < 2; p++) {
                    uint32_t addr = sbase + SM1_B + buf * B1_STAGE +
                        sw_off(nn_w + p * 16 + b_row_l, 2 * ks + b_ks_l);
                    LDSM_X4(b[2*p][0], b[2*p][1], b[2*p+1][0], b[2*p+1][1], addr);
                }
                uint32_t a[TT][4];
                #pragma unroll
                for (int t = 0; t < TT; t++) {
                    uint32_t addr = sbase + buf * A1_STAGE + t * 4096 +
                        sw_off(sm_w + a_row_l, 2 * ks + a_ks_l);
                    LDSM_X4(a[t][0], a[t][1], a[t][2], a[t][3], addr);
                }
                #pragma unroll
                for (int t = 0; t < TT; t++)
                    #pragma unroll
                    for (int n = 0; n < 4; n++)
                        IMMA16832(acci[t][n], a[t], b[n]);
            }
            buf = (buf == STG - 1) ? 0 : buf + 1;
            pbuf = (pbuf == STG - 1) ? 0 : pbuf + 1;
        }
        // fold: acci dies here, accf born here (disjoint live ranges)
        #pragma unroll
        for (int t = 0; t < TT; t++)
            #pragma unroll
            for (int n = 0; n < 4; n++)
                #pragma unroll
                for (int e = 0; e < 4; e++)
                    accf[t][n][e] = CFOLD * (float)acci[t][n][e];
    }

    // ---- fp16 phase: chunks 8-15, same ring, no drain ----
    {
        int buf = 8 % STG, pbuf = 10 % STG;
        for (int cc = 8; cc < 16; cc++) {
            if (cc < 15) asm volatile("cp.async.wait_group 1;" ::: "memory");
            else         asm volatile("cp.async.wait_group 0;" ::: "memory");
            __syncthreads();
            if (cc + 2 < 16) load_chunk(cc + 2, pbuf);

            #pragma unroll
            for (int ks = 0; ks < 4; ks++) {
                uint32_t b[4][2];
                #pragma unroll
                for (int p = 0; p < 2; p++) {
                    uint32_t addr = sbase + SM1_B + buf * B1_STAGE +
                        sw_off(nn_w + p * 16 + b_row_l, 2 * ks + b_ks_l);
                    LDSM_X4(b[2*p][0], b[2*p][1], b[2*p+1][0], b[2*p+1][1], addr);
                }
                uint32_t a[TT][4];
                #pragma unroll
                for (int t = 0; t < TT; t++) {
                    uint32_t addr = sbase + buf * A1_STAGE + t * 4096 +
                        sw_off(sm_w + a_row_l, 2 * ks + a_ks_l);
                    LDSM_X4(a[t][0], a[t][1], a[t][2], a[t][3], addr);
                }
                #pragma unroll
                for (int t = 0; t < TT; t++)
                    #pragma unroll
                    for (int n = 0; n < 4; n++)
                        MMAF16(accf[t][n], a[t], b[n]);
            }
            buf = (buf == STG - 1) ? 0 : buf + 1;
            pbuf = (pbuf == STG - 1) ? 0 : pbuf + 1;
        }
    }

    // ---- epilogue: scan, store spikes, flag tight margins ----
    const float alpha = alphap[0];
    const int row_in_m = lane >> 2;
    const int col_pair = (lane & 3) * 2;

    #pragma unroll
    for (int n = 0; n < 4; n++)
        #pragma unroll
        for (int rh = 0; rh < 2; rh++) {
            const int site = bm0 + sm_w + row_in_m + rh * 8;
            const int col  = bn0 + nn_w + n * 8 + col_pair;
            float v0 = 0.f, v1 = 0.f, m0 = 1e9f, m1 = 1e9f;
            #pragma unroll
            for (int t = 0; t < TT; t++) {
                v0 += alpha * (accf[t][n][rh * 2]     - v0);
                v1 += alpha * (accf[t][n][rh * 2 + 1] - v1);
                m0 = fminf(m0, fabsf(v0 - 1.0f));
                m1 = fminf(m1, fabsf(v1 - 1.0f));
                bool s0 = (v0 >= 1.0f), s1 = (v1 >= 1.0f);
                v0 = s0 ? 0.f : v0;
                v1 = s1 ? 0.f : v1;
                char2 pk;
                pk.x = s0 ? 1 : 0;
                pk.y = s1 ? 1 : 0;
                *(char2*)(outp + ((size_t)t * BROWS + site) * HH + col) = pk;
            }
            push_flag(m0 < EPS1, site * 2048 + col,     &g_cnt1, g_list1);
            push_flag(m1 < EPS1, site * 2048 + col + 1, &g_cnt1, g_list1);
        }
}

// ---------------- repair1: warp-per-neuron exact fp32 recompute ----------------
__global__ void repair_l1(const float* __restrict__ xraw,
                          const float* __restrict__ w1raw,
                          const float* __restrict__ alphap,
                          int8_t* __restrict__ s1)
{
    const int total = min(g_cnt1, LCAP);
    const float alpha = alphap[0];
    const int lane = threadIdx.x & 31;
    const int nwarp = (gridDim.x * blockDim.x) >> 5;
    for (int w = (blockIdx.x * blockDim.x + threadIdx.x) >> 5; w < total; w += nwarp) {
        const int e = g_list1[w];
        const int site = e >> 11, neuron = e & 2047;
        const float4* wp = (const float4*)(w1raw + (size_t)neuron * 512);
        float v = 0.f;
        for (int t = 0; t < TT; t++) {
            const float4* xp = (const float4*)(xraw + ((size_t)t * BROWS + site) * 512);
            float p = 0.f;
            #pragma unroll
            for (int k = 0; k < 4; k++) {
                float4 xv = xp[lane + k * 32], wv = wp[lane + k * 32];
                p += xv.x * wv.x + xv.y * wv.y + xv.z * wv.z + xv.w * wv.w;
            }
            #pragma unroll
            for (int o = 16; o; o >>= 1) p += __shfl_xor_sync(0xFFFFFFFF, p, o);
            v += alpha * (p - v);
            bool s = (v >= 1.0f);
            if (lane == 0)
                s1[((size_t)t * BROWS + site) * HH + neuron] = s ? 1 : 0;
            v = s ? 0.f : v;
        }
    }
}

// ---------------- layer2: int8 IMMA 2-digit + PLIF + flag, 2 CTAs/SM ----------------
__global__ __launch_bounds__(256, 2)
void gemm_plif_l2(const int8_t* __restrict__ A,
                  const int8_t* __restrict__ Bw,
                  const float* __restrict__ alphap,
                  float* __restrict__ outp)
{
    extern __shared__ __align__(128) unsigned char smem_raw[];
    const uint32_t sbase = smem_u32(smem_raw);

    const int tid  = threadIdx.x;
    const int lane = tid & 31;
    const int wid  = tid >> 5;
    const int wm   = wid & 1;
    const int wn   = wid >> 1;
    const int sm_w = wm * 16;
    const int nn_w = wn * 32;

    const int bm0 = blockIdx.x * MS2;
    const int bn0 = blockIdx.y * TN2;
    const int NC  = KB2 / BK2;          // 32; digit fold at cc==15

    // ---- precomputed loader offsets ----
    uint32_t ag[4], as[4], bg[4], bs[4];
    #pragma unroll
    for (int j = 0; j < 4; j++) {
        int i = tid + j * 256;
        int kseg = i & 7, site = (i >> 3) & 31, t = i >> 8;
        ag[j] = (uint32_t)((t * BROWS + bm0 + site) * 2048 + kseg * 16);
        as[j] = (uint32_t)(t * 4096 + sw_off(site, kseg));
        int n = i >> 3;
        bg[j] = (uint32_t)((bn0 + n) * 4096 + kseg * 16);
        bs[j] = sw_off(n, kseg);
    }

    auto load_chunk = [&](int cc, int buf) {
        const uint32_t acol = (cc & 15) * 128;
        const uint32_t bcol = cc * 128;
        const uint32_t abase = sbase + buf * A2_STAGE;
        const uint32_t bbase = sbase + SM2_B + buf * B2_STAGE;
        #pragma unroll
        for (int j = 0; j < 4; j++)
            CP_ASYNC16(abase + as[j], (const char*)A + ag[j] + acol);
        #pragma unroll
        for (int j = 0; j < 4; j++)
            CP_ASYNC16(bbase + bs[j], (const char*)Bw + bg[j] + bcol);
        CP_COMMIT();
    };

    int acc[TT][4][4];
    #pragma unroll
    for (int t = 0; t < TT; t++)
        #pragma unroll
        for (int n = 0; n < 4; n++)
            #pragma unroll
            for (int e = 0; e < 4; e++) acc[t][n][e] = 0;

    load_chunk(0, 0);
    load_chunk(1, 1);

    const int a_row_l = lane & 15;
    const int a_ks_l  = lane >> 4;
    const int b_row_l = (lane & 7) + ((lane & 16) >> 1);
    const int b_ks_l  = (lane >> 3) & 1;

    int buf = 0, pbuf = 2;
    for (int cc = 0; cc < NC; cc++) {
        if (cc < NC - 1) asm volatile("cp.async.wait_group 1;" ::: "memory");
        else             asm volatile("cp.async.wait_group 0;" ::: "memory");
        __syncthreads();
        if (cc + 2 < NC) load_chunk(cc + 2, pbuf);

        #pragma unroll
        for (int ks = 0; ks < 4; ks++) {
            uint32_t b[4][2];
            #pragma unroll
            for (int p = 0; p < 2; p++) {
                uint32_t addr = sbase + SM2_B + buf * B2_STAGE +
                    sw_off(nn_w + p * 16 + b_row_l, 2 * ks + b_ks_l);
                LDSM_X4(b[2*p][0], b[2*p][1], b[2*p+1][0], b[2*p+1][1], addr);
            }
            uint32_t a[TT][4];
            #pragma unroll
            for (int t = 0; t < TT; t++) {
                uint32_t addr = sbase + buf * A2_STAGE + t * 4096 +
                    sw_off(sm_w + a_row_l, 2 * ks + a_ks_l);
                LDSM_X4(a[t][0], a[t][1], a[t][2], a[t][3], addr);
            }
            #pragma unroll
            for (int t = 0; t < TT; t++)
                #pragma unroll
                for (int n = 0; n < 4; n++)
                    IMMA16832(acc[t][n], a[t], b[n]);
        }

        if (cc == 15) {                 // exact digit fold
            #pragma unroll
            for (int t = 0; t < TT; t++)
                #pragma unroll
                for (int n = 0; n < 4; n++)
                    #pragma unroll
                    for (int e = 0; e < 4; e++) acc[t][n][e] <<= 7;
        }
        buf = (buf == STG - 1) ? 0 : buf + 1;
        pbuf = (pbuf == STG - 1) ? 0 : pbuf + 1;
    }

    // PLIF scan on y = acc * 2^-15, store spikes, flag tight margins
    const float alpha = alphap[0];
    const int row_in_m = lane >> 2;
    const int col_pair = (lane & 3) * 2;
    #pragma unroll
    for (int n = 0; n < 4; n++)
        #pragma unroll
        for (int rh = 0; rh < 2; rh++) {
            const int site = bm0 + sm_w + row_in_m + rh * 8;
            const int col  = bn0 + nn_w + n * 8 + col_pair;
            float v0 = 0.f, v1 = 0.f, m0 = 1e9f, m1 = 1e9f;
            #pragma unroll
            for (int t = 0; t < TT; t++) {
                float y0 = (float)acc[t][n][rh * 2]     * W2SCALE;
                float y1 = (float)acc[t][n][rh * 2 + 1] * W2SCALE;
                v0 += alpha * (y0 - v0);
                v1 += alpha * (y1 - v1);
                m0 = fminf(m0, fabsf(v0 - 1.0f));
                m1 = fminf(m1, fabsf(v1 - 1.0f));
                bool s0 = (v0 >= 1.0f), s1v = (v1 >= 1.0f);
                v0 = s0 ? 0.f : v0;
                v1 = s1v ? 0.f : v1;
                *(float2*)(outp + ((size_t)t * BROWS + site) * DD + col) =
                    make_float2(s0 ? 1.0f : 0.0f, s1v ? 1.0f : 0.0f);
            }
            push_flag(m0 < EPS2, site * 512 + col,     &g_cnt2, g_list2);
            push_flag(m1 < EPS2, site * 512 + col + 1, &g_cnt2, g_list2);
        }
}

// ---------------- repair2: warp-per-neuron exact recompute of out ----------------
__global__ void repair_l2(const int8_t* __restrict__ s1,
                          const float* __restrict__ w2raw,
                          const float* __restrict__ alphap,
                          float* __restrict__ outp)
{
    const int total = min(g_cnt2, LCAP);
    const float alpha = alphap[0];
    const int lane = threadIdx.x & 31;
    const int nwarp = (gridDim.x * blockDim.x) >> 5;
    for (int w = (blockIdx.x * blockDim.x + threadIdx.x) >> 5; w < total; w += nwarp) {
        const int e = g_list2[w];
        const int site = e >> 9, col = e & 511;
        const float4* wp = (const float4*)(w2raw + (size_t)col * 2048);
        float v = 0.f;
        for (int t = 0; t < TT; t++) {
            const char4* sp = (const char4*)(s1 + ((size_t)t * BROWS + site) * HH);
            float p = 0.f;
            #pragma unroll
            for (int k = 0; k < 16; k++) {
                char4 sv = sp[lane + k * 32];
                float4 wv = wp[lane + k * 32];
                if (sv.x) p += wv.x;
                if (sv.y) p += wv.y;
                if (sv.z) p += wv.z;
                if (sv.w) p += wv.w;
            }
            #pragma unroll
            for (int o = 16; o; o >>= 1) p += __shfl_xor_sync(0xFFFFFFFF, p, o);
            v += alpha * (p - v);
            bool s = (v >= 1.0f);
            if (lane == 0)
                outp[((size_t)t * BROWS + site) * DD + col] = s ? 1.0f : 0.0f;
            v = s ? 0.f : v;
        }
    }
}

// ---------------- launch ----------------
extern "C" void kernel_launch(void* const* d_in, const int* in_sizes, int n_in,
                              void* d_out, int out_size)
{
    const float* x  = (const float*)d_in[0];
    const float* W1 = (const float*)d_in[1];
    const float* W2 = (const float*)d_in[2];
    const float* a1 = (const float*)d_in[3];
    const float* a2 = (const float*)d_in[4];
    float* out = (float*)d_out;

    __half *xh, *w1h;
    int8_t *xq, *w1q, *w2p, *s1;
    cudaGetSymbolAddress((void**)&xh,  g_xh);
    cudaGetSymbolAddress((void**)&xq,  g_xq);
    cudaGetSymbolAddress((void**)&w1h, g_w1h);
    cudaGetSymbolAddress((void**)&w1q, g_w1q);
    cudaGetSymbolAddress((void**)&w2p, g_w2);
    cudaGetSymbolAddress((void**)&s1,  g_s1);

    cudaFuncSetAttribute(gemm_plif_l1, cudaFuncAttributeMaxDynamicSharedMemorySize, SMEM1);
    cudaFuncSetAttribute(gemm_plif_l2, cudaFuncAttributeMaxDynamicSharedMemorySize, SMEM2);

    prep_x<<<(TT * BROWS * DD / 4) / 256, 256>>>((const float4*)x, xh, xq);
    prep_w1<<<(HH * DD) / 256, 256>>>(W1, w1h, w1q);
    pack_w2<<<(DD * HH) / 256, 256>>>(W2, w2p);

    // layer 1: int8 cross (K=1024) + fp16 hi*hi (K=512) -> s1 + flags
    dim3 g1(BROWS / MS1, HH / TN1);   // 256 x 16
    gemm_plif_l1<<<g1, 256, SMEM1>>>(xq, w1q, xh, w1h, a1, s1);
    repair_l1<<<512, 256>>>(x, W1, a1, s1);

    // layer 2: int8 IMMA 2-digit (K=4096) -> out + flags
    dim3 g2(BROWS / MS2, DD / TN2);   // 256 x 4
    gemm_plif_l2<<<g2, 256, SMEM2>>>(s1, w2p, a2, out);
    repair_l2<<<512, 256>>>(s1, W2, a2, out);
}

// round 15
// speedup vs baseline: 3.2562x; 1.0001x over previous
#include <cuda_runtime.h>
#include <cuda_bf16.h>
#include <cuda_fp16.h>
#include <cstdint>
#include <cstddef>

// ---------------- problem dims ----------------
constexpr int TT    = 4;
constexpr int BROWS = 8192;
constexpr int DD    = 512;
constexpr int HH    = 2048;
constexpr int KQ1   = 1024;           // layer1 int8 K: [q(lx) | q(x)]
constexpr int KH1   = 512;            // layer1 fp16 K (hi*hi)
constexpr int KA2   = 2048;           // layer2 A cols (s1 int8, wraps)
constexpr int KB2   = 4096;           // layer2 K: 2 digit planes x 2048 int8

// layer1 scales (fold constraint: 1/(IXL*IWH) == 1/(IXH*IWL), exact)
constexpr float IXH = 127.0f / 8.0f;
constexpr float IXL = 40000.0f;
constexpr float IWH = 127.0f / 0.32f;
constexpr float IWL = 1000000.0f;
constexpr float CFOLD = 8.0f / (127.0f * 1000000.0f);
constexpr float EPS1 = 2.5e-4f;
constexpr float W2SCALE = 1.0f / 32768.0f;
constexpr float EPS2 = 4e-3f;

// ---- layer1 tile: CTA 32 x 128 x 4t, 8 warps of 16x32, STG=3, 2 CTAs/SM ----
constexpr int MS1 = 32, TN1 = 128, STG = 3;
constexpr uint32_t A1_STAGE = 16384;
constexpr uint32_t B1_STAGE = 16384;
constexpr uint32_t SM1_B = STG * A1_STAGE;
constexpr uint32_t SMEM1 = STG * (A1_STAGE + B1_STAGE);   // 98304

// ---- layer2 tile ----
constexpr int MS2 = 32, TN2 = 128, BK2 = 128;
constexpr uint32_t A2_STAGE = 16384;
constexpr uint32_t B2_STAGE = 16384;
constexpr uint32_t SM2_B = STG * A2_STAGE;
constexpr uint32_t SMEM2 = STG * (A2_STAGE + B2_STAGE);   // 98304

// ---------------- scratch ----------------
__device__ __half  g_xh[(size_t)TT * BROWS * KH1];
__device__ int8_t  g_xq[(size_t)TT * BROWS * KQ1];
__device__ __half  g_w1h[(size_t)HH * KH1];
__device__ int8_t  g_w1q[(size_t)HH * KQ1];
__device__ int8_t  g_w2[(size_t)DD * KB2];
__device__ int8_t  g_s1[(size_t)TT * BROWS * HH];
constexpr int LCAP = 1 << 22;
__device__ int g_cnt1, g_cnt2;
__device__ int g_list1[LCAP];
__device__ int g_list2[LCAP];

// ---------------- PTX helpers ----------------
__device__ __forceinline__ uint32_t smem_u32(const void* p) {
    uint32_t a;
    asm("{ .reg .u64 t; cvta.to.shared.u64 t, %1; cvt.u32.u64 %0, t; }" : "=r"(a) : "l"(p));
    return a;
}
#define CP_ASYNC16(dst, src) \
    asm volatile("cp.async.cg.shared.global [%0], [%1], 16;" :: "r"(dst), "l"(src) : "memory")
#define CP_COMMIT() asm volatile("cp.async.commit_group;" ::: "memory")

#define LDSM_X4(r0, r1, r2, r3, addr)                                        \
    asm volatile("ldmatrix.sync.aligned.m8n8.x4.shared.b16 {%0,%1,%2,%3}, [%4];" \
        : "=r"(r0), "=r"(r1), "=r"(r2), "=r"(r3) : "r"(addr))

#define MMAF16(d, a, b)                                                      \
    asm volatile("mma.sync.aligned.m16n8k16.row.col.f32.f16.f16.f32 "        \
        "{%0,%1,%2,%3}, {%4,%5,%6,%7}, {%8,%9}, {%0,%1,%2,%3};"              \
        : "+f"((d)[0]), "+f"((d)[1]), "+f"((d)[2]), "+f"((d)[3])             \
        : "r"((a)[0]), "r"((a)[1]), "r"((a)[2]), "r"((a)[3]),                \
          "r"((b)[0]), "r"((b)[1]))

#define IMMA16832(d, a, b)                                                   \
    asm volatile("mma.sync.aligned.m16n8k32.row.col.s32.s8.s8.s32 "          \
        "{%0,%1,%2,%3}, {%4,%5,%6,%7}, {%8,%9}, {%0,%1,%2,%3};"              \
        : "+r"((d)[0]), "+r"((d)[1]), "+r"((d)[2]), "+r"((d)[3])             \
        : "r"((a)[0]), "r"((a)[1]), "r"((a)[2]), "r"((a)[3]),                \
          "r"((b)[0]), "r"((b)[1]))

__device__ __forceinline__ uint32_t sw_off(uint32_t row, uint32_t kseg) {
    return row * 128 + ((kseg ^ (row & 7)) << 4);
}
__device__ __forceinline__ int8_t q8(float v, float inv) {
    int q = __float2int_rn(v * inv);
    q = max(-127, min(127, q));
    return (int8_t)q;
}
// warp-aggregated flag push (flags are rare; early-out on no-flag)
__device__ __forceinline__ void push_flag(bool flag, int val, int* cnt, int* list) {
    unsigned bal = __ballot_sync(0xFFFFFFFF, flag);
    if (!bal) return;
    int leader = __ffs(bal) - 1;
    int lane = threadIdx.x & 31;
    int base = 0;
    if (lane == leader) base = atomicAdd(cnt, __popc(bal));
    base = __shfl_sync(0xFFFFFFFF, base, leader);
    if (flag) {
        int idx = base + __popc(bal & ((1u << lane) - 1));
        if (idx < LCAP) list[idx] = val;
    }
}

// ---------------- prep kernels ----------------
__global__ void prep_x(const float4* __restrict__ x,
                       __half* __restrict__ xh,
                       int8_t* __restrict__ xq)
{
    if (blockIdx.x == 0 && threadIdx.x == 0) { g_cnt1 = 0; g_cnt2 = 0; }
    size_t i = (size_t)blockIdx.x * blockDim.x + threadIdx.x;
    float4 v = x[i];
    int r = (int)(i >> 7);
    int d = ((int)i & 127) * 4;
    __half h0 = __float2half_rn(v.x), h1 = __float2half_rn(v.y);
    __half h2 = __float2half_rn(v.z), h3 = __float2half_rn(v.w);
    __half2* hp = (__half2*)(xh + (size_t)r * KH1 + d);
    hp[0] = __halves2half2(h0, h1);
    hp[1] = __halves2half2(h2, h3);
    float l0 = v.x - __half2float(h0), l1 = v.y - __half2float(h1);
    float l2 = v.z - __half2float(h2), l3 = v.w - __half2float(h3);
    char4 ql = make_char4(q8(l0, IXL), q8(l1, IXL), q8(l2, IXL), q8(l3, IXL));
    char4 qx = make_char4(q8(v.x, IXH), q8(v.y, IXH), q8(v.z, IXH), q8(v.w, IXH));
    *(char4*)(xq + (size_t)r * KQ1 + d)       = ql;
    *(char4*)(xq + (size_t)r * KQ1 + 512 + d) = qx;
}
// merged W prep: blocks [0, 4096) -> w1 split/quant; [4096, 8192) -> w2 digits
__global__ void prep_w(const float* __restrict__ w1,
                       __half* __restrict__ wh,
                       int8_t* __restrict__ wq,
                       const float* __restrict__ w2,
                       int8_t* __restrict__ o2)
{
    if (blockIdx.x < 4096) {
        size_t i = (size_t)blockIdx.x * blockDim.x + threadIdx.x;   // 2048*512
        int r = (int)(i >> 9);
        int d = (int)(i & 511);
        float v = w1[i];
        __half hb = __float2half_rn(v);
        float hi = __half2float(hb);
        wh[(size_t)r * KH1 + d] = hb;
        wq[(size_t)r * KQ1 + d]       = q8(hi, IWH);
        wq[(size_t)r * KQ1 + 512 + d] = q8(v - hi, IWL);
    } else {
        size_t i = (size_t)(blockIdx.x - 4096) * blockDim.x + threadIdx.x; // 512*2048
        int r = (int)(i >> 11);
        int c = (int)(i & 2047);
        int v = (int)lrintf(w2[i] * 32768.0f);
        v = max(-8192, min(8192, v));
        int d0 = ((v & 127) ^ 64) - 64;
        int d1 = (v - d0) >> 7;
        size_t base = (size_t)r * KB2;
        o2[base + c]        = (int8_t)d1;
        o2[base + 2048 + c] = (int8_t)d0;
    }
}

// ---------------- layer1: unified int8+fp16 pipeline, 2 CTAs/SM ----------------
__global__ __launch_bounds__(256, 2)
void gemm_plif_l1(const void* __restrict__ Aq, const void* __restrict__ Bq,
                  const void* __restrict__ Ah, const void* __restrict__ Bh,
                  const float* __restrict__ alphap,
                  int8_t* __restrict__ outp)
{
    extern __shared__ __align__(128) unsigned char smem_raw[];
    const uint32_t sbase = smem_u32(smem_raw);

    const int tid  = threadIdx.x;
    const int lane = tid & 31;
    const int wid  = tid >> 5;
    const int wm   = wid & 1;
    const int wn   = wid >> 1;
    const int sm_w = wm * 16;
    const int nn_w = wn * 32;

    const int bm0 = blockIdx.x * MS1;
    const int bn0 = blockIdx.y * TN1;

    const int a_row_l = lane & 15;
    const int a_ks_l  = lane >> 4;
    const int b_row_l = (lane & 7) + ((lane & 16) >> 1);
    const int b_ks_l  = (lane >> 3) & 1;

    // ---- hoisted LDSM addressing (loop-invariant row bases + masks) ----
    const uint32_t aRow  = sm_w + a_row_l;
    const uint32_t aB128 = sbase + aRow * 128;           // + buf*STAGE + t*4096 + kterm
    const uint32_t aMsk  = aRow & 7;
    uint32_t bB128[2], bMsk[2];
    #pragma unroll
    for (int p = 0; p < 2; p++) {
        uint32_t r = nn_w + p * 16 + b_row_l;
        bB128[p] = sbase + SM1_B + r * 128;
        bMsk[p]  = r & 7;
    }

    // ---- precomputed loader offsets (chunk-invariant) ----
    uint32_t ag[4], as[4], bg[4], bs[4];
    #pragma unroll
    for (int j = 0; j < 4; j++) {
        int i = tid + j * 256;
        int kseg = i & 7, site = (i >> 3) & 31, t = i >> 8;
        ag[j] = (uint32_t)((t * BROWS + bm0 + site) * 1024 + kseg * 16);
        as[j] = (uint32_t)(t * 4096 + sw_off(site, kseg));
        int n = i >> 3;
        bg[j] = (uint32_t)((bn0 + n) * 1024 + kseg * 16);
        bs[j] = sw_off(n, kseg);
    }

    auto load_chunk = [&](int cc, int buf) {
        const char* Ab = (const char*)((cc < 8) ? Aq : Ah);
        const char* Bb = (const char*)((cc < 8) ? Bq : Bh);
        const uint32_t bcol = (cc & 7) * 128;
        const uint32_t abase = sbase + buf * A1_STAGE;
        const uint32_t bbase = sbase + SM1_B + buf * B1_STAGE;
        #pragma unroll
        for (int j = 0; j < 4; j++)
            CP_ASYNC16(abase + as[j], Ab + ag[j] + bcol);
        #pragma unroll
        for (int j = 0; j < 4; j++)
            CP_ASYNC16(bbase + bs[j], Bb + bg[j] + bcol);
        CP_COMMIT();
    };

    float accf[TT][4][4];
    load_chunk(0, 0);
    load_chunk(1, 1);

    {   // ---- int8 phase: chunks 0-7 (ring continues into fp16 chunks) ----
        int acci[TT][4][4];
        #pragma unroll
        for (int t = 0; t < TT; t++)
            #pragma unroll
            for (int n = 0; n < 4; n++)
                #pragma unroll
                for (int e = 0; e < 4; e++) acci[t][n][e] = 0;

        int buf = 0, pbuf = 2;
        for (int cc = 0; cc < 8; cc++) {
            asm volatile("cp.async.wait_group 1;" ::: "memory");
            __syncthreads();
            load_chunk(cc + 2, pbuf);

            const uint32_t aOff = buf * A1_STAGE;
            const uint32_t bOff = buf * B1_STAGE;
            #pragma unroll
            for (int ks = 0; ks < 4; ks++) {
                uint32_t b[4][2];
                #pragma unroll
                for (int p = 0; p < 2; p++) {
                    uint32_t addr = bB128[p] + bOff +
                        (((2u * ks + b_ks_l) ^ bMsk[p]) << 4);
                    LDSM_X4(b[2*p][0], b[2*p][1], b[2*p+1][0], b[2*p+1][1], addr);
                }
                uint32_t a[TT][4];
                const uint32_t akt = ((2u * ks + a_ks_l) ^ aMsk) << 4;
                #pragma unroll
                for (int t = 0; t < TT; t++) {
                    uint32_t addr = aB128 + aOff + t * 4096 + akt;
                    LDSM_X4(a[t][0], a[t][1], a[t][2], a[t][3], addr);
                }
                #pragma unroll
                for (int t = 0; t < TT; t++)
                    #pragma unroll
                    for (int n = 0; n < 4; n++)
                        IMMA16832(acci[t][n], a[t], b[n]);
            }
            buf = (buf == STG - 1) ? 0 : buf + 1;
            pbuf = (pbuf == STG - 1) ? 0 : pbuf + 1;
        }
        // fold: acci dies here, accf born here (disjoint live ranges)
        #pragma unroll
        for (int t = 0; t < TT; t++)
            #pragma unroll
            for (int n = 0; n < 4; n++)
                #pragma unroll
                for (int e = 0; e < 4; e++)
                    accf[t][n][e] = CFOLD * (float)acci[t][n][e];
    }

    // ---- fp16 phase: chunks 8-15, same ring, no drain ----
    {
        int buf = 8 % STG, pbuf = 10 % STG;
        for (int cc = 8; cc < 16; cc++) {
            if (cc < 15) asm volatile("cp.async.wait_group 1;" ::: "memory");
            else         asm volatile("cp.async.wait_group 0;" ::: "memory");
            __syncthreads();
            if (cc + 2 < 16) load_chunk(cc + 2, pbuf);

            const uint32_t aOff = buf * A1_STAGE;
            const uint32_t bOff = buf * B1_STAGE;
            #pragma unroll
            for (int ks = 0; ks < 4; ks++) {
                uint32_t b[4][2];
                #pragma unroll
                for (int p = 0; p < 2; p++) {
                    uint32_t addr = bB128[p] + bOff +
                        (((2u * ks + b_ks_l) ^ bMsk[p]) << 4);
                    LDSM_X4(b[2*p][0], b[2*p][1], b[2*p+1][0], b[2*p+1][1], addr);
                }
                uint32_t a[TT][4];
                const uint32_t akt = ((2u * ks + a_ks_l) ^ aMsk) << 4;
                #pragma unroll
                for (int t = 0; t < TT; t++) {
                    uint32_t addr = aB128 + aOff + t * 4096 + akt;
                    LDSM_X4(a[t][0], a[t][1], a[t][2], a[t][3], addr);
                }
                #pragma unroll
                for (int t = 0; t < TT; t++)
                    #pragma unroll
                    for (int n = 0; n < 4; n++)
                        MMAF16(accf[t][n], a[t], b[n]);
            }
            buf = (buf == STG - 1) ? 0 : buf + 1;
            pbuf = (pbuf == STG - 1) ? 0 : pbuf + 1;
        }
    }

    // ---- epilogue: scan, store spikes, flag tight margins ----
    const float alpha = alphap[0];
    const int row_in_m = lane >> 2;
    const int col_pair = (lane & 3) * 2;

    #pragma unroll
    for (int n = 0; n < 4; n++)
        #pragma unroll
        for (int rh = 0; rh < 2; rh++) {
            const int site = bm0 + sm_w + row_in_m + rh * 8;
            const int col  = bn0 + nn_w + n * 8 + col_pair;
            float v0 = 0.f, v1 = 0.f, m0 = 1e9f, m1 = 1e9f;
            #pragma unroll
            for (int t = 0; t < TT; t++) {
                v0 += alpha * (accf[t][n][rh * 2]     - v0);
                v1 += alpha * (accf[t][n][rh * 2 + 1] - v1);
                m0 = fminf(m0, fabsf(v0 - 1.0f));
                m1 = fminf(m1, fabsf(v1 - 1.0f));
                bool s0 = (v0 >= 1.0f), s1 = (v1 >= 1.0f);
                v0 = s0 ? 0.f : v0;
                v1 = s1 ? 0.f : v1;
                char2 pk;
                pk.x = s0 ? 1 : 0;
                pk.y = s1 ? 1 : 0;
                *(char2*)(outp + ((size_t)t * BROWS + site) * HH + col) = pk;
            }
            push_flag(m0 < EPS1, site * 2048 + col,     &g_cnt1, g_list1);
            push_flag(m1 < EPS1, site * 2048 + col + 1, &g_cnt1, g_list1);
        }
}

// ---------------- repair1: warp-per-neuron exact fp32 recompute ----------------
__global__ void repair_l1(const float* __restrict__ xraw,
                          const float* __restrict__ w1raw,
                          const float* __restrict__ alphap,
                          int8_t* __restrict__ s1)
{
    const int total = min(g_cnt1, LCAP);
    const float alpha = alphap[0];
    const int lane = threadIdx.x & 31;
    const int nwarp = (gridDim.x * blockDim.x) >> 5;
    for (int w = (blockIdx.x * blockDim.x + threadIdx.x) >> 5; w < total; w += nwarp) {
        const int e = g_list1[w];
        const int site = e >> 11, neuron = e & 2047;
        const float4* wp = (const float4*)(w1raw + (size_t)neuron * 512);
        float v = 0.f;
        for (int t = 0; t < TT; t++) {
            const float4* xp = (const float4*)(xraw + ((size_t)t * BROWS + site) * 512);
            float p = 0.f;
            #pragma unroll
            for (int k = 0; k < 4; k++) {
                float4 xv = xp[lane + k * 32], wv = wp[lane + k * 32];
                p += xv.x * wv.x + xv.y * wv.y + xv.z * wv.z + xv.w * wv.w;
            }
            #pragma unroll
            for (int o = 16; o; o >>= 1) p += __shfl_xor_sync(0xFFFFFFFF, p, o);
            v += alpha * (p - v);
            bool s = (v >= 1.0f);
            if (lane == 0)
                s1[((size_t)t * BROWS + site) * HH + neuron] = s ? 1 : 0;
            v = s ? 0.f : v;
        }
    }
}

// ---------------- layer2: int8 IMMA 2-digit + PLIF + flag, 2 CTAs/SM ----------------
__global__ __launch_bounds__(256, 2)
void gemm_plif_l2(const int8_t* __restrict__ A,
                  const int8_t* __restrict__ Bw,
                  const float* __restrict__ alphap,
                  float* __restrict__ outp)
{
    extern __shared__ __align__(128) unsigned char smem_raw[];
    const uint32_t sbase = smem_u32(smem_raw);

    const int tid  = threadIdx.x;
    const int lane = tid & 31;
    const int wid  = tid >> 5;
    const int wm   = wid & 1;
    const int wn   = wid >> 1;
    const int sm_w = wm * 16;
    const int nn_w = wn * 32;

    const int bm0 = blockIdx.x * MS2;
    const int bn0 = blockIdx.y * TN2;
    const int NC  = KB2 / BK2;          // 32; digit fold at cc==15

    const int a_row_l = lane & 15;
    const int a_ks_l  = lane >> 4;
    const int b_row_l = (lane & 7) + ((lane & 16) >> 1);
    const int b_ks_l  = (lane >> 3) & 1;

    // hoisted LDSM addressing
    const uint32_t aRow  = sm_w + a_row_l;
    const uint32_t aB128 = sbase + aRow * 128;
    const uint32_t aMsk  = aRow & 7;
    uint32_t bB128[2], bMsk[2];
    #pragma unroll
    for (int p = 0; p < 2; p++) {
        uint32_t r = nn_w + p * 16 + b_row_l;
        bB128[p] = sbase + SM2_B + r * 128;
        bMsk[p]  = r & 7;
    }

    // precomputed loader offsets
    uint32_t ag[4], as[4], bg[4], bs[4];
    #pragma unroll
    for (int j = 0; j < 4; j++) {
        int i = tid + j * 256;
        int kseg = i & 7, site = (i >> 3) & 31, t = i >> 8;
        ag[j] = (uint32_t)((t * BROWS + bm0 + site) * 2048 + kseg * 16);
        as[j] = (uint32_t)(t * 4096 + sw_off(site, kseg));
        int n = i >> 3;
        bg[j] = (uint32_t)((bn0 + n) * 4096 + kseg * 16);
        bs[j] = sw_off(n, kseg);
    }

    auto load_chunk = [&](int cc, int buf) {
        const uint32_t acol = (cc & 15) * 128;
        const uint32_t bcol = cc * 128;
        const uint32_t abase = sbase + buf * A2_STAGE;
        const uint32_t bbase = sbase + SM2_B + buf * B2_STAGE;
        #pragma unroll
        for (int j = 0; j < 4; j++)
            CP_ASYNC16(abase + as[j], (const char*)A + ag[j] + acol);
        #pragma unroll
        for (int j = 0; j < 4; j++)
            CP_ASYNC16(bbase + bs[j], (const char*)Bw + bg[j] + bcol);
        CP_COMMIT();
    };

    int acc[TT][4][4];
    #pragma unroll
    for (int t = 0; t < TT; t++)
        #pragma unroll
        for (int n = 0; n < 4; n++)
            #pragma unroll
            for (int e = 0; e < 4; e++) acc[t][n][e] = 0;

    load_chunk(0, 0);
    load_chunk(1, 1);

    int buf = 0, pbuf = 2;
    for (int cc = 0; cc < NC; cc++) {
        if (cc < NC - 1) asm volatile("cp.async.wait_group 1;" ::: "memory");
        else             asm volatile("cp.async.wait_group 0;" ::: "memory");
        __syncthreads();
        if (cc + 2 < NC) load_chunk(cc + 2, pbuf);

        const uint32_t aOff = buf * A2_STAGE;
        const uint32_t bOff = buf * B2_STAGE;
        #pragma unroll
        for (int ks = 0; ks < 4; ks++) {
            uint32_t b[4][2];
            #pragma unroll
            for (int p = 0; p < 2; p++) {
                uint32_t addr = bB128[p] + bOff +
                    (((2u * ks + b_ks_l) ^ bMsk[p]) << 4);
                LDSM_X4(b[2*p][0], b[2*p][1], b[2*p+1][0], b[2*p+1][1], addr);
            }
            uint32_t a[TT][4];
            const uint32_t akt = ((2u * ks + a_ks_l) ^ aMsk) << 4;
            #pragma unroll
            for (int t = 0; t < TT; t++) {
                uint32_t addr = aB128 + aOff + t * 4096 + akt;
                LDSM_X4(a[t][0], a[t][1], a[t][2], a[t][3], addr);
            }
            #pragma unroll
            for (int t = 0; t < TT; t++)
                #pragma unroll
                for (int n = 0; n < 4; n++)
                    IMMA16832(acc[t][n], a[t], b[n]);
        }

        if (cc == 15) {                 // exact digit fold
            #pragma unroll
            for (int t = 0; t < TT; t++)
                #pragma unroll
                for (int n = 0; n < 4; n++)
                    #pragma unroll
                    for (int e = 0; e < 4; e++) acc[t][n][e] <<= 7;
        }
        buf = (buf == STG - 1) ? 0 : buf + 1;
        pbuf = (pbuf == STG - 1) ? 0 : pbuf + 1;
    }

    // PLIF scan on y = acc * 2^-15, store spikes, flag tight margins
    const float alpha = alphap[0];
    const int row_in_m = lane >> 2;
    const int col_pair = (lane & 3) * 2;
    #pragma unroll
    for (int n = 0; n < 4; n++)
        #pragma unroll
        for (int rh = 0; rh < 2; rh++) {
            const int site = bm0 + sm_w + row_in_m + rh * 8;
            const int col  = bn0 + nn_w + n * 8 + col_pair;
            float v0 = 0.f, v1 = 0.f, m0 = 1e9f, m1 = 1e9f;
            #pragma unroll
            for (int t = 0; t < TT; t++) {
                float y0 = (float)acc[t][n][rh * 2]     * W2SCALE;
                float y1 = (float)acc[t][n][rh * 2 + 1] * W2SCALE;
                v0 += alpha * (y0 - v0);
                v1 += alpha * (y1 - v1);
                m0 = fminf(m0, fabsf(v0 - 1.0f));
                m1 = fminf(m1, fabsf(v1 - 1.0f));
                bool s0 = (v0 >= 1.0f), s1v = (v1 >= 1.0f);
                v0 = s0 ? 0.f : v0;
                v1 = s1v ? 0.f : v1;
                *(float2*)(outp + ((size_t)t * BROWS + site) * DD + col) =
                    make_float2(s0 ? 1.0f : 0.0f, s1v ? 1.0f : 0.0f);
            }
            push_flag(m0 < EPS2, site * 512 + col,     &g_cnt2, g_list2);
            push_flag(m1 < EPS2, site * 512 + col + 1, &g_cnt2, g_list2);
        }
}

// ---------------- repair2: warp-per-neuron exact recompute of out ----------------
__global__ void repair_l2(const int8_t* __restrict__ s1,
                          const float* __restrict__ w2raw,
                          const float* __restrict__ alphap,
                          float* __restrict__ outp)
{
    const int total = min(g_cnt2, LCAP);
    const float alpha = alphap[0];
    const int lane = threadIdx.x & 31;
    const int nwarp = (gridDim.x * blockDim.x) >> 5;
    for (int w = (blockIdx.x * blockDim.x + threadIdx.x) >> 5; w < total; w += nwarp) {
        const int e = g_list2[w];
        const int site = e >> 9, col = e & 511;
        const float4* wp = (const float4*)(w2raw + (size_t)col * 2048);
        float v = 0.f;
        for (int t = 0; t < TT; t++) {
            const char4* sp = (const char4*)(s1 + ((size_t)t * BROWS + site) * HH);
            float p = 0.f;
            #pragma unroll
            for (int k = 0; k < 16; k++) {
                char4 sv = sp[lane + k * 32];
                float4 wv = wp[lane + k * 32];
                if (sv.x) p += wv.x;
                if (sv.y) p += wv.y;
                if (sv.z) p += wv.z;
                if (sv.w) p += wv.w;
            }
            #pragma unroll
            for (int o = 16; o; o >>= 1) p += __shfl_xor_sync(0xFFFFFFFF, p, o);
            v += alpha * (p - v);
            bool s = (v >= 1.0f);
            if (lane == 0)
                outp[((size_t)t * BROWS + site) * DD + col] = s ? 1.0f : 0.0f;
            v = s ? 0.f : v;
        }
    }
}

// ---------------- launch ----------------
extern "C" void kernel_launch(void* const* d_in, const int* in_sizes, int n_in,
                              void* d_out, int out_size)
{
    const float* x  = (const float*)d_in[0];
    const float* W1 = (const float*)d_in[1];
    const float* W2 = (const float*)d_in[2];
    const float* a1 = (const float*)d_in[3];
    const float* a2 = (const float*)d_in[4];
    float* out = (float*)d_out;

    __half *xh, *w1h;
    int8_t *xq, *w1q, *w2p, *s1;
    cudaGetSymbolAddress((void**)&xh,  g_xh);
    cudaGetSymbolAddress((void**)&xq,  g_xq);
    cudaGetSymbolAddress((void**)&w1h, g_w1h);
    cudaGetSymbolAddress((void**)&w1q, g_w1q);
    cudaGetSymbolAddress((void**)&w2p, g_w2);
    cudaGetSymbolAddress((void**)&s1,  g_s1);

    cudaFuncSetAttribute(gemm_plif_l1, cudaFuncAttributeMaxDynamicSharedMemorySize, SMEM1);
    cudaFuncSetAttribute(gemm_plif_l2, cudaFuncAttributeMaxDynamicSharedMemorySize, SMEM2);

    prep_x<<<(TT * BROWS * DD / 4) / 256, 256>>>((const float4*)x, xh, xq);
    prep_w<<<8192, 256>>>(W1, w1h, w1q, W2, w2p);

    // layer 1: int8 cross (K=1024) + fp16 hi*hi (K=512) -> s1 + flags
    dim3 g1(BROWS / MS1, HH / TN1);   // 256 x 16
    gemm_plif_l1<<<g1, 256, SMEM1>>>(xq, w1q, xh, w1h, a1, s1);
    repair_l1<<<128, 256>>>(x, W1, a1, s1);

    // layer 2: int8 IMMA 2-digit (K=4096) -> out + flags
    dim3 g2(BROWS / MS2, DD / TN2);   // 256 x 4
    gemm_plif_l2<<<g2, 256, SMEM2>>>(s1, w2p, a2, out);
    repair_l2<<<128, 256>>>(s1, W2, a2, out);
}